// round 1
// baseline (speedup 1.0000x reference)
#include <cuda_runtime.h>
#include <math.h>

#define BB 2
#define NN 512
#define CS 128
#define CH 16
#define HH 12
#define PQ 4
#define VV 8
#define HC (HH*CH)            /* 192 */
#define CATD (HH*(CH+VV*4))   /* 576 */

// ---------------- scratch (device globals; no allocations allowed) -----------
__device__ float q_g  [BB*HH*NN*CH];
__device__ float k_g  [BB*HH*NN*CH];
__device__ float v_g  [BB*HH*NN*CH];
__device__ float qp_g [BB*HH*NN*PQ*3];
__device__ float kp_g [BB*HH*NN*PQ*3];
__device__ float vp_g [BB*HH*NN*VV*3];
__device__ float sqq_g[BB*HH*NN];
__device__ float sqk_g[BB*HH*NN];
__device__ float cat_g[BB*NN*CATD];

// ---------------- kernel 1: projections + frame rotation --------------------
// 8 rows per block, 256 threads. Tasks: 192 q cols, 384 kv cols, 48 qp points,
// 144 kvp points (each point = 3 dots + rotation).
__global__ __launch_bounds__(256) void proj_kernel(
    const float* __restrict__ s,  const float* __restrict__ R,
    const float* __restrict__ t,
    const float* __restrict__ Wq,  const float* __restrict__ bq,
    const float* __restrict__ Wkv, const float* __restrict__ bkv,
    const float* __restrict__ Wqp, const float* __restrict__ bqp,
    const float* __restrict__ Wkvp,const float* __restrict__ bkvp)
{
    __shared__ float s_sm[8][CS];
    __shared__ float Rt_sm[8][12];
    __shared__ float sqq_sm[8][HH];
    __shared__ float sqk_sm[8][HH];

    const int tid  = threadIdx.x;
    const int row0 = blockIdx.x * 8;

    for (int idx = tid; idx < 8*CS; idx += 256)
        s_sm[idx>>7][idx&127] = s[(long)row0*CS + idx];
    for (int idx = tid; idx < 8*12; idx += 256) {
        int r = idx/12, c = idx%12;
        Rt_sm[r][c] = (c < 9) ? R[(long)(row0+r)*9 + c] : t[(long)(row0+r)*3 + (c-9)];
    }
    for (int idx = tid; idx < 8*HH; idx += 256) {
        sqq_sm[idx/HH][idx%HH] = 0.f;
        sqk_sm[idx/HH][idx%HH] = 0.f;
    }
    __syncthreads();

    for (int task = tid; task < 768; task += 256) {
        if (task < 576) {
            // ---- plain linear columns (q: 192, kv: 384) ----
            const float* W; float bias; int stride; int col;
            if (task < 192) { col = task;       W = Wq  + col; stride = HC;   bias = bq[col];  }
            else            { col = task - 192; W = Wkv + col; stride = 2*HC; bias = bkv[col]; }
            float acc[8];
            #pragma unroll
            for (int r = 0; r < 8; r++) acc[r] = bias;
            for (int k = 0; k < CS; k++) {
                float w = W[(long)k*stride];
                #pragma unroll
                for (int r = 0; r < 8; r++) acc[r] += w * s_sm[r][k];
            }
            if (task < 192) {
                int h = col >> 4, c = col & 15;
                #pragma unroll
                for (int r = 0; r < 8; r++) {
                    int row = row0 + r, b = row >> 9, n = row & 511;
                    q_g[((long)(b*HH+h)*NN + n)*CH + c] = acc[r];
                }
            } else {
                int h = col >> 5, cc = col & 31;
                #pragma unroll
                for (int r = 0; r < 8; r++) {
                    int row = row0 + r, b = row >> 9, n = row & 511;
                    long base = ((long)(b*HH+h)*NN + n)*CH;
                    if (cc < 16) k_g[base + cc]        = acc[r];
                    else         v_g[base + (cc-16)]   = acc[r];
                }
            }
        } else {
            // ---- point columns: 3 dots + rotation ----
            int p; const float* W; int npts; const float* bvec; int is_qp;
            if (task < 624) { p = task - 576; W = Wqp;  npts = 48;  bvec = bqp;  is_qp = 1; }
            else            { p = task - 624; W = Wkvp; npts = 144; bvec = bkvp; is_qp = 0; }
            float d0[8], d1[8], d2[8];
            float b0 = bvec[0*npts+p], b1 = bvec[1*npts+p], b2 = bvec[2*npts+p];
            #pragma unroll
            for (int r = 0; r < 8; r++) { d0[r] = b0; d1[r] = b1; d2[r] = b2; }
            for (int k = 0; k < CS; k++) {
                float w0 = W[(long)k*3*npts + 0*npts + p];
                float w1 = W[(long)k*3*npts + 1*npts + p];
                float w2 = W[(long)k*3*npts + 2*npts + p];
                #pragma unroll
                for (int r = 0; r < 8; r++) {
                    float sv = s_sm[r][k];
                    d0[r] += w0*sv; d1[r] += w1*sv; d2[r] += w2*sv;
                }
            }
            #pragma unroll
            for (int r = 0; r < 8; r++) {
                int row = row0 + r, b = row >> 9, n = row & 511;
                float x0 = Rt_sm[r][0]*d0[r] + Rt_sm[r][1]*d1[r] + Rt_sm[r][2]*d2[r] + Rt_sm[r][9];
                float x1 = Rt_sm[r][3]*d0[r] + Rt_sm[r][4]*d1[r] + Rt_sm[r][5]*d2[r] + Rt_sm[r][10];
                float x2 = Rt_sm[r][6]*d0[r] + Rt_sm[r][7]*d1[r] + Rt_sm[r][8]*d2[r] + Rt_sm[r][11];
                if (is_qp) {
                    int h = p / PQ, pp = p % PQ;
                    long base = ((long)(b*HH+h)*NN + n)*(PQ*3) + pp*3;
                    qp_g[base+0] = x0; qp_g[base+1] = x1; qp_g[base+2] = x2;
                    atomicAdd(&sqq_sm[r][h], x0*x0 + x1*x1 + x2*x2);
                } else {
                    int h = p / (PQ+VV), idx = p % (PQ+VV);
                    if (idx < PQ) {
                        long base = ((long)(b*HH+h)*NN + n)*(PQ*3) + idx*3;
                        kp_g[base+0] = x0; kp_g[base+1] = x1; kp_g[base+2] = x2;
                        atomicAdd(&sqk_sm[r][h], x0*x0 + x1*x1 + x2*x2);
                    } else {
                        long base = ((long)(b*HH+h)*NN + n)*(VV*3) + (idx-PQ)*3;
                        vp_g[base+0] = x0; vp_g[base+1] = x1; vp_g[base+2] = x2;
                    }
                }
            }
        }
    }
    __syncthreads();
    for (int idx = tid; idx < 8*HH; idx += 256) {
        int r = idx/HH, h = idx%HH;
        int row = row0 + r, b = row >> 9, n = row & 511;
        sqq_g[(long)(b*HH+h)*NN + n] = sqq_sm[r][h];
        sqk_g[(long)(b*HH+h)*NN + n] = sqk_sm[r][h];
    }
}

// ---------------- kernel 2: attention (flash-style, 1 warp / query row) -----
__global__ __launch_bounds__(256) void attn_kernel(
    const float* __restrict__ pair_mask,
    const float* __restrict__ R, const float* __restrict__ t,
    const float* __restrict__ head_weights)
{
    __shared__ float ks [128*17];
    __shared__ float kps[128*13];
    __shared__ float vs [128*17];
    __shared__ float vps[128*25];
    __shared__ float sqks[128];
    __shared__ float red[8][41];

    const int tid  = threadIdx.x;
    const int lane = tid & 31;
    const int warp = tid >> 5;
    const int b = blockIdx.z, h = blockIdx.y;
    const int i = blockIdx.x*8 + warp;
    const int bh = b*HH + h;

    float q[CH], qp[12];
    {
        const float* qr  = q_g  + ((long)bh*NN + i)*CH;
        const float* qpr = qp_g + ((long)bh*NN + i)*12;
        #pragma unroll
        for (int c = 0; c < CH; c++) q[c] = qr[c];
        #pragma unroll
        for (int c = 0; c < 12; c++) qp[c] = qpr[c];
    }
    const float sqq = sqq_g[(long)bh*NN + i];
    const float hwv = log1pf(__expf(head_weights[h])) * 0.1360827634879543f; // sqrt(1/54)
    const float c1  = -0.5f * hwv;
    const float qs  = 0.14433756729740643f;  // 1/sqrt(48)
    const float* maskrow = pair_mask + ((long)b*NN + i)*NN;

    float m = -1e30f, ls = 0.f;
    float acc[40];
    #pragma unroll
    for (int x = 0; x < 40; x++) acc[x] = 0.f;

    for (int jt = 0; jt < 4; jt++) {
        const int j0 = jt * 128;
        __syncthreads();
        {
            const float* kb = k_g + ((long)bh*NN + j0)*CH;
            const float* vb = v_g + ((long)bh*NN + j0)*CH;
            for (int idx = tid; idx < 128*CH; idx += 256) {
                int j = idx >> 4, c = idx & 15;
                ks[j*17+c] = kb[idx];
                vs[j*17+c] = vb[idx];
            }
            const float* kpb = kp_g + ((long)bh*NN + j0)*12;
            for (int idx = tid; idx < 128*12; idx += 256) {
                int j = idx/12, c = idx - j*12;
                kps[j*13+c] = kpb[idx];
            }
            const float* vpb = vp_g + ((long)bh*NN + j0)*24;
            for (int idx = tid; idx < 128*24; idx += 256) {
                int j = idx/24, c = idx - j*24;
                vps[j*25+c] = vpb[idx];
            }
            for (int idx = tid; idx < 128; idx += 256)
                sqks[idx] = sqk_g[(long)bh*NN + j0 + idx];
        }
        __syncthreads();

        #pragma unroll
        for (int u = 0; u < 4; u++) {
            const int j = u*32 + lane;
            float qk = 0.f;
            #pragma unroll
            for (int c = 0; c < 16; c++) qk += q[c]*ks[j*17+c];
            float cross = 0.f;
            #pragma unroll
            for (int c = 0; c < 12; c++) cross += qp[c]*kps[j*13+c];
            float mval  = maskrow[j0 + j];
            float logit = qk*qs + c1*(sqq + sqks[j]) + hwv*cross + 100000.f*(mval - 1.f);

            float mnew = fmaxf(m, logit);
            if (mnew > m) {
                float corr = __expf(m - mnew);
                ls *= corr;
                #pragma unroll
                for (int x = 0; x < 40; x++) acc[x] *= corr;
                m = mnew;
            }
            float p = __expf(logit - m);
            ls += p;
            #pragma unroll
            for (int c = 0; c < 16; c++) acc[c]    += p*vs[j*17+c];
            #pragma unroll
            for (int c = 0; c < 24; c++) acc[16+c] += p*vps[j*25+c];
        }
    }

    // ---- cross-lane merge ----
    float M = m;
    #pragma unroll
    for (int o = 16; o; o >>= 1) M = fmaxf(M, __shfl_xor_sync(0xffffffffu, M, o));
    float cl  = __expf(m - M);
    float lss = ls * cl;
    #pragma unroll
    for (int o = 16; o; o >>= 1) lss += __shfl_xor_sync(0xffffffffu, lss, o);
    #pragma unroll
    for (int x = 0; x < 40; x++) {
        float val = acc[x] * cl;
        #pragma unroll
        for (int o = 16; o; o >>= 1) val += __shfl_xor_sync(0xffffffffu, val, o);
        if (lane == 0) red[warp][x] = val;
    }
    if (lane == 0) red[warp][40] = lss;
    __syncwarp();

    const float sinv = 1.f / red[warp][40];
    const long rowbase = ((long)(b*NN + i))*CATD;
    if (lane < 16) {
        cat_g[rowbase + h*CH + lane] = red[warp][lane] * sinv;
    } else if (lane < 24) {
        const int vv = lane - 16;
        float gx = red[warp][16 + vv*3 + 0] * sinv;
        float gy = red[warp][16 + vv*3 + 1] * sinv;
        float gz = red[warp][16 + vv*3 + 2] * sinv;
        const float* Rr = R + ((long)(b*NN + i))*9;
        const float* tr = t + ((long)(b*NN + i))*3;
        float lx = Rr[0]*gx + Rr[3]*gy + Rr[6]*gz - tr[0];
        float ly = Rr[1]*gx + Rr[4]*gy + Rr[7]*gz - tr[1];
        float lz = Rr[2]*gx + Rr[5]*gy + Rr[8]*gz - tr[2];
        float nrm = sqrtf(lx*lx + ly*ly + lz*lz + 1e-8f);
        cat_g[rowbase + HC +   0 + h*VV + vv] = lx;
        cat_g[rowbase + HC +  96 + h*VV + vv] = ly;
        cat_g[rowbase + HC + 192 + h*VV + vv] = lz;
        cat_g[rowbase + HC + 288 + h*VV + vv] = nrm;
    }
}

// ---------------- kernel 3: output projection --------------------------------
__global__ __launch_bounds__(256) void out_kernel(
    const float* __restrict__ Wout, const float* __restrict__ bout,
    float* __restrict__ out)
{
    __shared__ float csm[8*CATD];
    const int tid  = threadIdx.x;
    const int col  = tid & 127;
    const int half = tid >> 7;
    const int row0 = blockIdx.x * 8;

    for (int idx = tid; idx < 8*CATD; idx += 256)
        csm[idx] = cat_g[(long)row0*CATD + idx];
    __syncthreads();

    float acc[4] = {0.f, 0.f, 0.f, 0.f};
    const float* cb = csm + half*4*CATD;
    for (int k = 0; k < CATD; k++) {
        float w = Wout[(long)k*CS + col];
        #pragma unroll
        for (int r = 0; r < 4; r++) acc[r] += cb[r*CATD + k] * w;
    }
    float bb = bout[col];
    #pragma unroll
    for (int r = 0; r < 4; r++)
        out[(long)(row0 + half*4 + r)*CS + col] = acc[r] + bb;
}

// ---------------- launcher ----------------------------------------------------
extern "C" void kernel_launch(void* const* d_in, const int* in_sizes, int n_in,
                              void* d_out, int out_size)
{
    const float* s    = (const float*)d_in[0];
    const float* R    = (const float*)d_in[1];
    const float* t    = (const float*)d_in[2];
    const float* mask = (const float*)d_in[3];
    const float* Wq   = (const float*)d_in[4];
    const float* bq   = (const float*)d_in[5];
    const float* Wkv  = (const float*)d_in[6];
    const float* bkv  = (const float*)d_in[7];
    const float* Wqp  = (const float*)d_in[8];
    const float* bqp  = (const float*)d_in[9];
    const float* Wkvp = (const float*)d_in[10];
    const float* bkvp = (const float*)d_in[11];
    const float* hwts = (const float*)d_in[12];
    const float* Wout = (const float*)d_in[13];
    const float* bout = (const float*)d_in[14];
    float* out = (float*)d_out;

    proj_kernel<<<(BB*NN)/8, 256>>>(s, R, t, Wq, bq, Wkv, bkv, Wqp, bqp, Wkvp, bkvp);
    attn_kernel<<<dim3(NN/8, HH, BB), 256>>>(mask, R, t, hwts);
    out_kernel<<<(BB*NN)/8, 256>>>(Wout, bout, out);
}

// round 2
// speedup vs baseline: 1.0356x; 1.0356x over previous
#include <cuda_runtime.h>
#include <math.h>

#define BB 2
#define NN 512
#define CS 128
#define CH 16
#define HH 12
#define PQ 4
#define VV 8
#define HC (HH*CH)            /* 192 */
#define CATD (HH*(CH+VV*4))   /* 576 */

// ---------------- scratch (device globals; no allocations allowed) -----------
__device__ float q_g  [BB*HH*NN*CH];
__device__ float k_g  [BB*HH*NN*CH];
__device__ float v_g  [BB*HH*NN*CH];
__device__ float qp_g [BB*HH*NN*PQ*3];
__device__ float kp_g [BB*HH*NN*PQ*3];
__device__ float vp_g [BB*HH*NN*VV*3];
__device__ float sqq_g[BB*HH*NN];
__device__ float sqk_g[BB*HH*NN];
__device__ float cat_g[BB*NN*CATD];

// ---------------- kernel 1: projections + frame rotation --------------------
// 8 rows per block; tasks split across blockIdx.y (3 groups of 256).
__global__ __launch_bounds__(256) void proj_kernel(
    const float* __restrict__ s,  const float* __restrict__ R,
    const float* __restrict__ t,
    const float* __restrict__ Wq,  const float* __restrict__ bq,
    const float* __restrict__ Wkv, const float* __restrict__ bkv,
    const float* __restrict__ Wqp, const float* __restrict__ bqp,
    const float* __restrict__ Wkvp,const float* __restrict__ bkvp)
{
    __shared__ float s_sm[8][CS];
    __shared__ float Rt_sm[8][12];
    __shared__ float sqq_sm[8][HH];
    __shared__ float sqk_sm[8][HH];

    const int tid  = threadIdx.x;
    const int row0 = blockIdx.x * 8;

    for (int idx = tid; idx < 8*CS; idx += 256)
        s_sm[idx>>7][idx&127] = s[(long)row0*CS + idx];
    for (int idx = tid; idx < 8*12; idx += 256) {
        int r = idx/12, c = idx%12;
        Rt_sm[r][c] = (c < 9) ? R[(long)(row0+r)*9 + c] : t[(long)(row0+r)*3 + (c-9)];
    }
    for (int idx = tid; idx < 8*HH; idx += 256) {
        sqq_sm[idx/HH][idx%HH] = 0.f;
        sqk_sm[idx/HH][idx%HH] = 0.f;
    }
    __syncthreads();

    const int task = blockIdx.y*256 + tid;   // one round per block
    if (task < 768) {
        if (task < 576) {
            const float* W; float bias; int stride; int col;
            if (task < 192) { col = task;       W = Wq  + col; stride = HC;   bias = bq[col];  }
            else            { col = task - 192; W = Wkv + col; stride = 2*HC; bias = bkv[col]; }
            float acc[8];
            #pragma unroll
            for (int r = 0; r < 8; r++) acc[r] = bias;
            #pragma unroll 8
            for (int k = 0; k < CS; k++) {
                float w = __ldg(&W[(long)k*stride]);
                #pragma unroll
                for (int r = 0; r < 8; r++) acc[r] += w * s_sm[r][k];
            }
            if (task < 192) {
                int h = col >> 4, c = col & 15;
                #pragma unroll
                for (int r = 0; r < 8; r++) {
                    int row = row0 + r, b = row >> 9, n = row & 511;
                    q_g[((long)(b*HH+h)*NN + n)*CH + c] = acc[r];
                }
            } else {
                int h = col >> 5, cc = col & 31;
                #pragma unroll
                for (int r = 0; r < 8; r++) {
                    int row = row0 + r, b = row >> 9, n = row & 511;
                    long base = ((long)(b*HH+h)*NN + n)*CH;
                    if (cc < 16) k_g[base + cc]        = acc[r];
                    else         v_g[base + (cc-16)]   = acc[r];
                }
            }
        } else {
            int p; const float* W; int npts; const float* bvec; int is_qp;
            if (task < 624) { p = task - 576; W = Wqp;  npts = 48;  bvec = bqp;  is_qp = 1; }
            else            { p = task - 624; W = Wkvp; npts = 144; bvec = bkvp; is_qp = 0; }
            float d0[8], d1[8], d2[8];
            float b0 = bvec[0*npts+p], b1 = bvec[1*npts+p], b2 = bvec[2*npts+p];
            #pragma unroll
            for (int r = 0; r < 8; r++) { d0[r] = b0; d1[r] = b1; d2[r] = b2; }
            #pragma unroll 4
            for (int k = 0; k < CS; k++) {
                float w0 = __ldg(&W[(long)k*3*npts + 0*npts + p]);
                float w1 = __ldg(&W[(long)k*3*npts + 1*npts + p]);
                float w2 = __ldg(&W[(long)k*3*npts + 2*npts + p]);
                #pragma unroll
                for (int r = 0; r < 8; r++) {
                    float sv = s_sm[r][k];
                    d0[r] += w0*sv; d1[r] += w1*sv; d2[r] += w2*sv;
                }
            }
            #pragma unroll
            for (int r = 0; r < 8; r++) {
                int row = row0 + r, b = row >> 9, n = row & 511;
                float x0 = Rt_sm[r][0]*d0[r] + Rt_sm[r][1]*d1[r] + Rt_sm[r][2]*d2[r] + Rt_sm[r][9];
                float x1 = Rt_sm[r][3]*d0[r] + Rt_sm[r][4]*d1[r] + Rt_sm[r][5]*d2[r] + Rt_sm[r][10];
                float x2 = Rt_sm[r][6]*d0[r] + Rt_sm[r][7]*d1[r] + Rt_sm[r][8]*d2[r] + Rt_sm[r][11];
                if (is_qp) {
                    int h = p / PQ, pp = p % PQ;
                    long base = ((long)(b*HH+h)*NN + n)*(PQ*3) + pp*3;
                    qp_g[base+0] = x0; qp_g[base+1] = x1; qp_g[base+2] = x2;
                    atomicAdd(&sqq_sm[r][h], x0*x0 + x1*x1 + x2*x2);
                } else {
                    int h = p / (PQ+VV), idx = p % (PQ+VV);
                    if (idx < PQ) {
                        long base = ((long)(b*HH+h)*NN + n)*(PQ*3) + idx*3;
                        kp_g[base+0] = x0; kp_g[base+1] = x1; kp_g[base+2] = x2;
                        atomicAdd(&sqk_sm[r][h], x0*x0 + x1*x1 + x2*x2);
                    } else {
                        long base = ((long)(b*HH+h)*NN + n)*(VV*3) + (idx-PQ)*3;
                        vp_g[base+0] = x0; vp_g[base+1] = x1; vp_g[base+2] = x2;
                    }
                }
            }
        }
    }
    __syncthreads();
    // only the task group that computed points (groups 2 for qp lives in group 2?
    // qp tasks are 576..623 (group 2), kp in 624..767 (group 2). Only blockIdx.y==2
    // has nonzero sums; others would write zeros and race. Guard:
    if (blockIdx.y == 2) {
        for (int idx = tid; idx < 8*HH; idx += 256) {
            int r = idx/HH, h = idx%HH;
            int row = row0 + r, b = row >> 9, n = row & 511;
            sqq_g[(long)(b*HH+h)*NN + n] = sqq_sm[r][h];
            sqk_g[(long)(b*HH+h)*NN + n] = sqk_sm[r][h];
        }
    }
}

// ---------------- kernel 2: attention (flash-style, 2 query rows / warp) -----
#define SKV 20   /* k/v tile stride (4*odd) */
#define SKP 12   /* kp stride (4*3, odd multiplier) */
#define SVP 28   /* vp stride (4*7) */

__global__ __launch_bounds__(256) void attn_kernel(
    const float* __restrict__ pair_mask,
    const float* __restrict__ R, const float* __restrict__ t,
    const float* __restrict__ head_weights)
{
    __shared__ __align__(16) float ks [128*SKV];
    __shared__ __align__(16) float vs [128*SKV];
    __shared__ __align__(16) float kps[128*SKP];
    __shared__ __align__(16) float vps[128*SVP];
    __shared__ float sqks[128];
    __shared__ float msk[16*128];
    __shared__ float red[8][2][41];

    const int tid  = threadIdx.x;
    const int lane = tid & 31;
    const int warp = tid >> 5;
    const int b = blockIdx.z, h = blockIdx.y;
    const int i0 = blockIdx.x*16 + warp*2;
    const int bh = b*HH + h;

    float q0[CH], q1[CH], qp0[12], qp1[12];
    {
        const float4* qr0  = (const float4*)(q_g  + ((long)bh*NN + i0)*CH);
        const float4* qr1  = (const float4*)(q_g  + ((long)bh*NN + i0+1)*CH);
        #pragma unroll
        for (int c = 0; c < 4; c++) {
            float4 a = qr0[c]; q0[4*c]=a.x; q0[4*c+1]=a.y; q0[4*c+2]=a.z; q0[4*c+3]=a.w;
            float4 d = qr1[c]; q1[4*c]=d.x; q1[4*c+1]=d.y; q1[4*c+2]=d.z; q1[4*c+3]=d.w;
        }
        const float4* pr0 = (const float4*)(qp_g + ((long)bh*NN + i0)*12);
        const float4* pr1 = (const float4*)(qp_g + ((long)bh*NN + i0+1)*12);
        #pragma unroll
        for (int c = 0; c < 3; c++) {
            float4 a = pr0[c]; qp0[4*c]=a.x; qp0[4*c+1]=a.y; qp0[4*c+2]=a.z; qp0[4*c+3]=a.w;
            float4 d = pr1[c]; qp1[4*c]=d.x; qp1[4*c+1]=d.y; qp1[4*c+2]=d.z; qp1[4*c+3]=d.w;
        }
    }
    const float sqq0 = sqq_g[(long)bh*NN + i0];
    const float sqq1 = sqq_g[(long)bh*NN + i0+1];
    const float hwv = log1pf(__expf(head_weights[h])) * 0.1360827634879543f; // sqrt(1/54)
    const float c1  = -0.5f * hwv;
    const float qs  = 0.14433756729740643f;  // 1/sqrt(48)

    float m0 = -1e30f, ls0 = 0.f, m1 = -1e30f, ls1 = 0.f;
    float acc0[40], acc1[40];
    #pragma unroll
    for (int x = 0; x < 40; x++) { acc0[x] = 0.f; acc1[x] = 0.f; }

    for (int jt = 0; jt < 4; jt++) {
        const int j0 = jt * 128;
        __syncthreads();
        {
            const float* kb = k_g + ((long)bh*NN + j0)*CH;
            const float* vb = v_g + ((long)bh*NN + j0)*CH;
            for (int idx = tid; idx < 128*CH; idx += 256) {
                int j = idx >> 4, c = idx & 15;
                ks[j*SKV+c] = kb[idx];
                vs[j*SKV+c] = vb[idx];
            }
            const float* kpb = kp_g + ((long)bh*NN + j0)*12;
            for (int idx = tid; idx < 128*12; idx += 256)
                kps[idx] = kpb[idx];
            const float* vpb = vp_g + ((long)bh*NN + j0)*24;
            for (int idx = tid; idx < 128*24; idx += 256) {
                int j = idx/24, c = idx - j*24;
                vps[j*SVP+c] = vpb[idx];
            }
            for (int idx = tid; idx < 128; idx += 256)
                sqks[idx] = sqk_g[(long)bh*NN + j0 + idx];
            // mask tile: rows are this block's 16 i values
            const long mbase = ((long)b*NN + blockIdx.x*16)*NN + j0;
            for (int idx = tid; idx < 16*128; idx += 256) {
                int r = idx >> 7, c = idx & 127;
                msk[idx] = 100000.f * (pair_mask[mbase + (long)r*NN + c] - 1.f);
            }
        }
        __syncthreads();

        #pragma unroll
        for (int u = 0; u < 4; u++) {
            const int j = u*32 + lane;
            const float4* k4  = (const float4*)(ks  + j*SKV);
            const float4* kp4 = (const float4*)(kps + j*SKP);
            float qk0 = 0.f, qk1 = 0.f, cr0 = 0.f, cr1 = 0.f;
            #pragma unroll
            for (int c = 0; c < 4; c++) {
                float4 kk = k4[c];
                qk0 += q0[4*c]*kk.x + q0[4*c+1]*kk.y + q0[4*c+2]*kk.z + q0[4*c+3]*kk.w;
                qk1 += q1[4*c]*kk.x + q1[4*c+1]*kk.y + q1[4*c+2]*kk.z + q1[4*c+3]*kk.w;
            }
            #pragma unroll
            for (int c = 0; c < 3; c++) {
                float4 kk = kp4[c];
                cr0 += qp0[4*c]*kk.x + qp0[4*c+1]*kk.y + qp0[4*c+2]*kk.z + qp0[4*c+3]*kk.w;
                cr1 += qp1[4*c]*kk.x + qp1[4*c+1]*kk.y + qp1[4*c+2]*kk.z + qp1[4*c+3]*kk.w;
            }
            const float sk = sqks[j];
            float logit0 = qk0*qs + c1*(sqq0 + sk) + hwv*cr0 + msk[(warp*2+0)*128 + j];
            float logit1 = qk1*qs + c1*(sqq1 + sk) + hwv*cr1 + msk[(warp*2+1)*128 + j];

            float mn0 = fmaxf(m0, logit0);
            if (mn0 > m0) {
                float corr = __expf(m0 - mn0);
                ls0 *= corr;
                #pragma unroll
                for (int x = 0; x < 40; x++) acc0[x] *= corr;
                m0 = mn0;
            }
            float p0 = __expf(logit0 - m0);
            ls0 += p0;
            float mn1 = fmaxf(m1, logit1);
            if (mn1 > m1) {
                float corr = __expf(m1 - mn1);
                ls1 *= corr;
                #pragma unroll
                for (int x = 0; x < 40; x++) acc1[x] *= corr;
                m1 = mn1;
            }
            float p1 = __expf(logit1 - m1);
            ls1 += p1;

            const float4* v4  = (const float4*)(vs  + j*SKV);
            #pragma unroll
            for (int c = 0; c < 4; c++) {
                float4 vv = v4[c];
                acc0[4*c]   += p0*vv.x; acc0[4*c+1] += p0*vv.y;
                acc0[4*c+2] += p0*vv.z; acc0[4*c+3] += p0*vv.w;
                acc1[4*c]   += p1*vv.x; acc1[4*c+1] += p1*vv.y;
                acc1[4*c+2] += p1*vv.z; acc1[4*c+3] += p1*vv.w;
            }
            const float4* vp4 = (const float4*)(vps + j*SVP);
            #pragma unroll
            for (int c = 0; c < 6; c++) {
                float4 vv = vp4[c];
                acc0[16+4*c]   += p0*vv.x; acc0[16+4*c+1] += p0*vv.y;
                acc0[16+4*c+2] += p0*vv.z; acc0[16+4*c+3] += p0*vv.w;
                acc1[16+4*c]   += p1*vv.x; acc1[16+4*c+1] += p1*vv.y;
                acc1[16+4*c+2] += p1*vv.z; acc1[16+4*c+3] += p1*vv.w;
            }
        }
    }

    // ---- cross-lane merge (i0) ----
    {
        float M = m0;
        #pragma unroll
        for (int o = 16; o; o >>= 1) M = fmaxf(M, __shfl_xor_sync(0xffffffffu, M, o));
        float cl  = __expf(m0 - M);
        float lss = ls0 * cl;
        #pragma unroll
        for (int o = 16; o; o >>= 1) lss += __shfl_xor_sync(0xffffffffu, lss, o);
        #pragma unroll
        for (int x = 0; x < 40; x++) {
            float val = acc0[x] * cl;
            #pragma unroll
            for (int o = 16; o; o >>= 1) val += __shfl_xor_sync(0xffffffffu, val, o);
            if (lane == 0) red[warp][0][x] = val;
        }
        if (lane == 0) red[warp][0][40] = lss;
    }
    // ---- cross-lane merge (i1) ----
    {
        float M = m1;
        #pragma unroll
        for (int o = 16; o; o >>= 1) M = fmaxf(M, __shfl_xor_sync(0xffffffffu, M, o));
        float cl  = __expf(m1 - M);
        float lss = ls1 * cl;
        #pragma unroll
        for (int o = 16; o; o >>= 1) lss += __shfl_xor_sync(0xffffffffu, lss, o);
        #pragma unroll
        for (int x = 0; x < 40; x++) {
            float val = acc1[x] * cl;
            #pragma unroll
            for (int o = 16; o; o >>= 1) val += __shfl_xor_sync(0xffffffffu, val, o);
            if (lane == 0) red[warp][1][x] = val;
        }
        if (lane == 0) red[warp][1][40] = lss;
    }
    __syncwarp();

    #pragma unroll
    for (int ii = 0; ii < 2; ii++) {
        const int i = i0 + ii;
        const float sinv = 1.f / red[warp][ii][40];
        const long rowbase = ((long)(b*NN + i))*CATD;
        if (lane < 16) {
            cat_g[rowbase + h*CH + lane] = red[warp][ii][lane] * sinv;
        } else if (lane < 24) {
            const int vv = lane - 16;
            float gx = red[warp][ii][16 + vv*3 + 0] * sinv;
            float gy = red[warp][ii][16 + vv*3 + 1] * sinv;
            float gz = red[warp][ii][16 + vv*3 + 2] * sinv;
            const float* Rr = R + ((long)(b*NN + i))*9;
            const float* tr = t + ((long)(b*NN + i))*3;
            float lx = Rr[0]*gx + Rr[3]*gy + Rr[6]*gz - tr[0];
            float ly = Rr[1]*gx + Rr[4]*gy + Rr[7]*gz - tr[1];
            float lz = Rr[2]*gx + Rr[5]*gy + Rr[8]*gz - tr[2];
            float nrm = sqrtf(lx*lx + ly*ly + lz*lz + 1e-8f);
            cat_g[rowbase + HC +   0 + h*VV + vv] = lx;
            cat_g[rowbase + HC +  96 + h*VV + vv] = ly;
            cat_g[rowbase + HC + 192 + h*VV + vv] = lz;
            cat_g[rowbase + HC + 288 + h*VV + vv] = nrm;
        }
    }
}

// ---------------- kernel 3: output projection --------------------------------
__global__ __launch_bounds__(256) void out_kernel(
    const float* __restrict__ Wout, const float* __restrict__ bout,
    float* __restrict__ out)
{
    __shared__ float csm[4*CATD];
    const int tid  = threadIdx.x;
    const int col  = tid & 127;
    const int half = tid >> 7;
    const int row0 = blockIdx.x * 4;

    for (int idx = tid; idx < 4*CATD; idx += 256)
        csm[idx] = cat_g[(long)row0*CATD + idx];
    __syncthreads();

    float acc[2] = {0.f, 0.f};
    const float* cb = csm + half*2*CATD;
    #pragma unroll 8
    for (int k = 0; k < CATD; k++) {
        float w = __ldg(&Wout[(long)k*CS + col]);
        acc[0] += cb[k] * w;
        acc[1] += cb[CATD + k] * w;
    }
    float bb = bout[col];
    out[(long)(row0 + half*2 + 0)*CS + col] = acc[0] + bb;
    out[(long)(row0 + half*2 + 1)*CS + col] = acc[1] + bb;
}

// ---------------- launcher ----------------------------------------------------
extern "C" void kernel_launch(void* const* d_in, const int* in_sizes, int n_in,
                              void* d_out, int out_size)
{
    const float* s    = (const float*)d_in[0];
    const float* R    = (const float*)d_in[1];
    const float* t    = (const float*)d_in[2];
    const float* mask = (const float*)d_in[3];
    const float* Wq   = (const float*)d_in[4];
    const float* bq   = (const float*)d_in[5];
    const float* Wkv  = (const float*)d_in[6];
    const float* bkv  = (const float*)d_in[7];
    const float* Wqp  = (const float*)d_in[8];
    const float* bqp  = (const float*)d_in[9];
    const float* Wkvp = (const float*)d_in[10];
    const float* bkvp = (const float*)d_in[11];
    const float* hwts = (const float*)d_in[12];
    const float* Wout = (const float*)d_in[13];
    const float* bout = (const float*)d_in[14];
    float* out = (float*)d_out;

    proj_kernel<<<dim3((BB*NN)/8, 3), 256>>>(s, R, t, Wq, bq, Wkv, bkv, Wqp, bqp, Wkvp, bkvp);
    attn_kernel<<<dim3(NN/16, HH, BB), 256>>>(mask, R, t, hwts);
    out_kernel<<<(BB*NN)/4, 256>>>(Wout, bout, out);
}

// round 3
// speedup vs baseline: 1.2479x; 1.2050x over previous
#include <cuda_runtime.h>
#include <math.h>

#define BB 2
#define NN 512
#define CS 128
#define CH 16
#define HH 12
#define PQ 4
#define VV 8
#define HC (HH*CH)            /* 192 */
#define CATD (HH*(CH+VV*4))   /* 576 */

// ---------------- scratch (device globals; no allocations allowed) -----------
__device__ float q_g  [BB*HH*NN*CH];
__device__ float k_g  [BB*HH*NN*CH];
__device__ float v_g  [BB*HH*NN*CH];
__device__ float qp_g [BB*HH*NN*PQ*3];
__device__ float kp_g [BB*HH*NN*PQ*3];
__device__ float vp_g [BB*HH*NN*VV*3];
__device__ float sqq_g[BB*HH*NN];
__device__ float sqk_g[BB*HH*NN];
__device__ float cat_g[BB*NN*CATD];

// ---------------- kernel 1: projections + frame rotation --------------------
// 4 rows per block; tasks split across blockIdx.y (3 groups of 256).
#define PR 4
__global__ __launch_bounds__(256) void proj_kernel(
    const float* __restrict__ s,  const float* __restrict__ R,
    const float* __restrict__ t,
    const float* __restrict__ Wq,  const float* __restrict__ bq,
    const float* __restrict__ Wkv, const float* __restrict__ bkv,
    const float* __restrict__ Wqp, const float* __restrict__ bqp,
    const float* __restrict__ Wkvp,const float* __restrict__ bkvp)
{
    __shared__ float s_sm[PR][CS];
    __shared__ float Rt_sm[PR][12];
    __shared__ float sqq_sm[PR][HH];
    __shared__ float sqk_sm[PR][HH];

    const int tid  = threadIdx.x;
    const int row0 = blockIdx.x * PR;

    for (int idx = tid; idx < PR*CS; idx += 256)
        s_sm[idx>>7][idx&127] = s[(long)row0*CS + idx];
    if (tid < PR*12) {
        int r = tid/12, c = tid%12;
        Rt_sm[r][c] = (c < 9) ? R[(long)(row0+r)*9 + c] : t[(long)(row0+r)*3 + (c-9)];
    }
    if (tid < PR*HH) {
        sqq_sm[tid/HH][tid%HH] = 0.f;
        sqk_sm[tid/HH][tid%HH] = 0.f;
    }
    __syncthreads();

    const int task = blockIdx.y*256 + tid;
    if (task < 768) {
        if (task < 576) {
            const float* W; float bias; int stride; int col;
            if (task < 192) { col = task;       W = Wq  + col; stride = HC;   bias = bq[col];  }
            else            { col = task - 192; W = Wkv + col; stride = 2*HC; bias = bkv[col]; }
            float acc[PR];
            #pragma unroll
            for (int r = 0; r < PR; r++) acc[r] = bias;
            #pragma unroll 16
            for (int k = 0; k < CS; k++) {
                float w = __ldg(&W[(long)k*stride]);
                #pragma unroll
                for (int r = 0; r < PR; r++) acc[r] += w * s_sm[r][k];
            }
            if (task < 192) {
                int h = col >> 4, c = col & 15;
                #pragma unroll
                for (int r = 0; r < PR; r++) {
                    int row = row0 + r, b = row >> 9, n = row & 511;
                    q_g[((long)(b*HH+h)*NN + n)*CH + c] = acc[r];
                }
            } else {
                int h = col >> 5, cc = col & 31;
                #pragma unroll
                for (int r = 0; r < PR; r++) {
                    int row = row0 + r, b = row >> 9, n = row & 511;
                    long base = ((long)(b*HH+h)*NN + n)*CH;
                    if (cc < 16) k_g[base + cc]        = acc[r];
                    else         v_g[base + (cc-16)]   = acc[r];
                }
            }
        } else {
            int p; const float* W; int npts; const float* bvec; int is_qp;
            if (task < 624) { p = task - 576; W = Wqp;  npts = 48;  bvec = bqp;  is_qp = 1; }
            else            { p = task - 624; W = Wkvp; npts = 144; bvec = bkvp; is_qp = 0; }
            float d0[PR], d1[PR], d2[PR];
            float b0 = bvec[0*npts+p], b1 = bvec[1*npts+p], b2 = bvec[2*npts+p];
            #pragma unroll
            for (int r = 0; r < PR; r++) { d0[r] = b0; d1[r] = b1; d2[r] = b2; }
            #pragma unroll 8
            for (int k = 0; k < CS; k++) {
                float w0 = __ldg(&W[(long)k*3*npts + 0*npts + p]);
                float w1 = __ldg(&W[(long)k*3*npts + 1*npts + p]);
                float w2 = __ldg(&W[(long)k*3*npts + 2*npts + p]);
                #pragma unroll
                for (int r = 0; r < PR; r++) {
                    float sv = s_sm[r][k];
                    d0[r] += w0*sv; d1[r] += w1*sv; d2[r] += w2*sv;
                }
            }
            #pragma unroll
            for (int r = 0; r < PR; r++) {
                int row = row0 + r, b = row >> 9, n = row & 511;
                float x0 = Rt_sm[r][0]*d0[r] + Rt_sm[r][1]*d1[r] + Rt_sm[r][2]*d2[r] + Rt_sm[r][9];
                float x1 = Rt_sm[r][3]*d0[r] + Rt_sm[r][4]*d1[r] + Rt_sm[r][5]*d2[r] + Rt_sm[r][10];
                float x2 = Rt_sm[r][6]*d0[r] + Rt_sm[r][7]*d1[r] + Rt_sm[r][8]*d2[r] + Rt_sm[r][11];
                if (is_qp) {
                    int h = p / PQ, pp = p % PQ;
                    long base = ((long)(b*HH+h)*NN + n)*(PQ*3) + pp*3;
                    qp_g[base+0] = x0; qp_g[base+1] = x1; qp_g[base+2] = x2;
                    atomicAdd(&sqq_sm[r][h], x0*x0 + x1*x1 + x2*x2);
                } else {
                    int h = p / (PQ+VV), idx = p % (PQ+VV);
                    if (idx < PQ) {
                        long base = ((long)(b*HH+h)*NN + n)*(PQ*3) + idx*3;
                        kp_g[base+0] = x0; kp_g[base+1] = x1; kp_g[base+2] = x2;
                        atomicAdd(&sqk_sm[r][h], x0*x0 + x1*x1 + x2*x2);
                    } else {
                        long base = ((long)(b*HH+h)*NN + n)*(VV*3) + (idx-PQ)*3;
                        vp_g[base+0] = x0; vp_g[base+1] = x1; vp_g[base+2] = x2;
                    }
                }
            }
        }
    }
    __syncthreads();
    if (blockIdx.y == 2 && tid < PR*HH) {
        int r = tid/HH, h = tid%HH;
        int row = row0 + r, b = row >> 9, n = row & 511;
        sqq_g[(long)(b*HH+h)*NN + n] = sqq_sm[r][h];
        sqk_g[(long)(b*HH+h)*NN + n] = sqk_sm[r][h];
    }
}

// ---------------- kernel 2: attention (two-phase softmax, 2 queries / warp) --
#define SKV 20   /* k/v tile stride in floats (float4 stride 5, odd) */
#define SKP 12   /* kp stride (float4 stride 3, odd) */
#define SVP 28   /* vp stride (float4 stride 7, odd) */

__global__ __launch_bounds__(256) void attn_kernel(
    const float* __restrict__ pair_mask,
    const float* __restrict__ R, const float* __restrict__ t,
    const float* __restrict__ head_weights)
{
    // phase A: ks[0..2559], kps[2560..4095], sqks[4096..4223], msk[4224..6271]
    // phase B: vs[0..2559],  vps[2560..6143]
    __shared__ __align__(16) float pool[6272];
    __shared__ float red[8][2][41];
    float* const ks   = pool;
    float* const kps  = pool + 2560;
    float* const sqks = pool + 4096;
    float* const msk  = pool + 4224;
    float* const vs   = pool;
    float* const vps  = pool + 2560;

    const int tid  = threadIdx.x;
    const int lane = tid & 31;
    const int warp = tid >> 5;
    const int b = blockIdx.z, h = blockIdx.y;
    const int i0 = blockIdx.x*16 + warp*2;
    const int bh = b*HH + h;

    const float hwv = log1pf(__expf(head_weights[h])) * 0.1360827634879543f; // sqrt(1/54)
    const float c1  = -0.5f * hwv;
    const float qs  = 0.14433756729740643f;  // 1/sqrt(48)

    float q0[CH], q1[CH], qp0[12], qp1[12];
    {
        const float4* qr0 = (const float4*)(q_g + ((long)bh*NN + i0)*CH);
        const float4* qr1 = (const float4*)(q_g + ((long)bh*NN + i0+1)*CH);
        #pragma unroll
        for (int c = 0; c < 4; c++) {
            float4 a = qr0[c];
            q0[4*c]=a.x*qs; q0[4*c+1]=a.y*qs; q0[4*c+2]=a.z*qs; q0[4*c+3]=a.w*qs;
            float4 d = qr1[c];
            q1[4*c]=d.x*qs; q1[4*c+1]=d.y*qs; q1[4*c+2]=d.z*qs; q1[4*c+3]=d.w*qs;
        }
        const float4* pr0 = (const float4*)(qp_g + ((long)bh*NN + i0)*12);
        const float4* pr1 = (const float4*)(qp_g + ((long)bh*NN + i0+1)*12);
        #pragma unroll
        for (int c = 0; c < 3; c++) {
            float4 a = pr0[c];
            qp0[4*c]=a.x*hwv; qp0[4*c+1]=a.y*hwv; qp0[4*c+2]=a.z*hwv; qp0[4*c+3]=a.w*hwv;
            float4 d = pr1[c];
            qp1[4*c]=d.x*hwv; qp1[4*c+1]=d.y*hwv; qp1[4*c+2]=d.z*hwv; qp1[4*c+3]=d.w*hwv;
        }
    }
    const float base0 = c1 * sqq_g[(long)bh*NN + i0];
    const float base1 = c1 * sqq_g[(long)bh*NN + i0+1];

    float la0[16], la1[16];

    // ---------------- phase A: all logits ----------------
    #pragma unroll
    for (int jt = 0; jt < 4; jt++) {
        const int j0 = jt * 128;
        __syncthreads();
        {
            const float4* kb  = (const float4*)(k_g  + ((long)bh*NN + j0)*CH);
            for (int idx = tid; idx < 512; idx += 256)
                ((float4*)(ks + (idx>>2)*SKV))[idx&3] = kb[idx];
            const float4* kpb = (const float4*)(kp_g + ((long)bh*NN + j0)*12);
            for (int idx = tid; idx < 384; idx += 256) {
                int j = idx/3, c = idx - j*3;
                ((float4*)(kps + j*SKP))[c] = kpb[idx];
            }
            if (tid < 128) sqks[tid] = sqk_g[(long)bh*NN + j0 + tid];
            const long mbase = ((long)b*NN + blockIdx.x*16)*NN + j0;
            const float4* mb = (const float4*)(pair_mask + mbase);
            for (int idx = tid; idx < 512; idx += 256) {
                int r = idx >> 5, c = idx & 31;
                float4 mm = mb[(r*NN>>2) + c];
                float4 o;
                o.x = 100000.f*(mm.x-1.f); o.y = 100000.f*(mm.y-1.f);
                o.z = 100000.f*(mm.z-1.f); o.w = 100000.f*(mm.w-1.f);
                ((float4*)(msk + r*128))[c] = o;
            }
        }
        __syncthreads();

        #pragma unroll
        for (int u = 0; u < 4; u++) {
            const int j = u*32 + lane;
            const float4* k4  = (const float4*)(ks  + j*SKV);
            const float4* kp4 = (const float4*)(kps + j*SKP);
            float qk0 = 0.f, qk1 = 0.f;
            #pragma unroll
            for (int c = 0; c < 4; c++) {
                float4 kk = k4[c];
                qk0 += q0[4*c]*kk.x + q0[4*c+1]*kk.y + q0[4*c+2]*kk.z + q0[4*c+3]*kk.w;
                qk1 += q1[4*c]*kk.x + q1[4*c+1]*kk.y + q1[4*c+2]*kk.z + q1[4*c+3]*kk.w;
            }
            #pragma unroll
            for (int c = 0; c < 3; c++) {
                float4 kk = kp4[c];
                qk0 += qp0[4*c]*kk.x + qp0[4*c+1]*kk.y + qp0[4*c+2]*kk.z + qp0[4*c+3]*kk.w;
                qk1 += qp1[4*c]*kk.x + qp1[4*c+1]*kk.y + qp1[4*c+2]*kk.z + qp1[4*c+3]*kk.w;
            }
            const float skc = c1 * sqks[j];
            la0[jt*4+u] = qk0 + skc + base0 + msk[(warp*2+0)*128 + j];
            la1[jt*4+u] = qk1 + skc + base1 + msk[(warp*2+1)*128 + j];
        }
    }

    // ---------------- exact softmax (max, exp, sum) ----------------
    float ls0, ls1;
    {
        float M0 = la0[0], M1 = la1[0];
        #pragma unroll
        for (int x = 1; x < 16; x++) { M0 = fmaxf(M0, la0[x]); M1 = fmaxf(M1, la1[x]); }
        #pragma unroll
        for (int o = 16; o; o >>= 1) {
            M0 = fmaxf(M0, __shfl_xor_sync(0xffffffffu, M0, o));
            M1 = fmaxf(M1, __shfl_xor_sync(0xffffffffu, M1, o));
        }
        ls0 = 0.f; ls1 = 0.f;
        #pragma unroll
        for (int x = 0; x < 16; x++) {
            la0[x] = __expf(la0[x] - M0); ls0 += la0[x];
            la1[x] = __expf(la1[x] - M1); ls1 += la1[x];
        }
    }

    // ---------------- phase B: weighted accumulation ----------------
    float acc0[40], acc1[40];
    #pragma unroll
    for (int x = 0; x < 40; x++) { acc0[x] = 0.f; acc1[x] = 0.f; }

    #pragma unroll
    for (int jt = 0; jt < 4; jt++) {
        const int j0 = jt * 128;
        __syncthreads();
        {
            const float4* vb  = (const float4*)(v_g  + ((long)bh*NN + j0)*CH);
            for (int idx = tid; idx < 512; idx += 256)
                ((float4*)(vs + (idx>>2)*SKV))[idx&3] = vb[idx];
            const float4* vpb = (const float4*)(vp_g + ((long)bh*NN + j0)*24);
            for (int idx = tid; idx < 768; idx += 256) {
                int j = idx/6, c = idx - j*6;
                ((float4*)(vps + j*SVP))[c] = vpb[idx];
            }
        }
        __syncthreads();

        #pragma unroll
        for (int u = 0; u < 4; u++) {
            const int j = u*32 + lane;
            const float p0 = la0[jt*4+u];
            const float p1 = la1[jt*4+u];
            const float4* v4  = (const float4*)(vs  + j*SKV);
            #pragma unroll
            for (int c = 0; c < 4; c++) {
                float4 vv = v4[c];
                acc0[4*c]   += p0*vv.x; acc0[4*c+1] += p0*vv.y;
                acc0[4*c+2] += p0*vv.z; acc0[4*c+3] += p0*vv.w;
                acc1[4*c]   += p1*vv.x; acc1[4*c+1] += p1*vv.y;
                acc1[4*c+2] += p1*vv.z; acc1[4*c+3] += p1*vv.w;
            }
            const float4* vp4 = (const float4*)(vps + j*SVP);
            #pragma unroll
            for (int c = 0; c < 6; c++) {
                float4 vv = vp4[c];
                acc0[16+4*c]   += p0*vv.x; acc0[16+4*c+1] += p0*vv.y;
                acc0[16+4*c+2] += p0*vv.z; acc0[16+4*c+3] += p0*vv.w;
                acc1[16+4*c]   += p1*vv.x; acc1[16+4*c+1] += p1*vv.y;
                acc1[16+4*c+2] += p1*vv.z; acc1[16+4*c+3] += p1*vv.w;
            }
        }
    }

    // ---------------- cross-lane merge + finalize ----------------
    {
        float lss = ls0;
        #pragma unroll
        for (int o = 16; o; o >>= 1) lss += __shfl_xor_sync(0xffffffffu, lss, o);
        #pragma unroll
        for (int x = 0; x < 40; x++) {
            float val = acc0[x];
            #pragma unroll
            for (int o = 16; o; o >>= 1) val += __shfl_xor_sync(0xffffffffu, val, o);
            if (lane == 0) red[warp][0][x] = val;
        }
        if (lane == 0) red[warp][0][40] = lss;
    }
    {
        float lss = ls1;
        #pragma unroll
        for (int o = 16; o; o >>= 1) lss += __shfl_xor_sync(0xffffffffu, lss, o);
        #pragma unroll
        for (int x = 0; x < 40; x++) {
            float val = acc1[x];
            #pragma unroll
            for (int o = 16; o; o >>= 1) val += __shfl_xor_sync(0xffffffffu, val, o);
            if (lane == 0) red[warp][1][x] = val;
        }
        if (lane == 0) red[warp][1][40] = lss;
    }
    __syncwarp();

    #pragma unroll
    for (int ii = 0; ii < 2; ii++) {
        const int i = i0 + ii;
        const float sinv = 1.f / red[warp][ii][40];
        const long rowbase = ((long)(b*NN + i))*CATD;
        if (lane < 16) {
            cat_g[rowbase + h*CH + lane] = red[warp][ii][lane] * sinv;
        } else if (lane < 24) {
            const int vv = lane - 16;
            float gx = red[warp][ii][16 + vv*3 + 0] * sinv;
            float gy = red[warp][ii][16 + vv*3 + 1] * sinv;
            float gz = red[warp][ii][16 + vv*3 + 2] * sinv;
            const float* Rr = R + ((long)(b*NN + i))*9;
            const float* tr = t + ((long)(b*NN + i))*3;
            float lx = Rr[0]*gx + Rr[3]*gy + Rr[6]*gz - tr[0];
            float ly = Rr[1]*gx + Rr[4]*gy + Rr[7]*gz - tr[1];
            float lz = Rr[2]*gx + Rr[5]*gy + Rr[8]*gz - tr[2];
            float nrm = sqrtf(lx*lx + ly*ly + lz*lz + 1e-8f);
            cat_g[rowbase + HC +   0 + h*VV + vv] = lx;
            cat_g[rowbase + HC +  96 + h*VV + vv] = ly;
            cat_g[rowbase + HC + 192 + h*VV + vv] = lz;
            cat_g[rowbase + HC + 288 + h*VV + vv] = nrm;
        }
    }
}

// ---------------- kernel 3: output projection --------------------------------
__global__ __launch_bounds__(256) void out_kernel(
    const float* __restrict__ Wout, const float* __restrict__ bout,
    float* __restrict__ out)
{
    __shared__ float csm[4*CATD];
    const int tid  = threadIdx.x;
    const int col  = tid & 127;
    const int half = tid >> 7;
    const int row0 = blockIdx.x * 4;

    for (int idx = tid; idx < 4*CATD; idx += 256)
        csm[idx] = cat_g[(long)row0*CATD + idx];
    __syncthreads();

    float acc[2] = {0.f, 0.f};
    const float* cb = csm + half*2*CATD;
    #pragma unroll 8
    for (int k = 0; k < CATD; k++) {
        float w = __ldg(&Wout[(long)k*CS + col]);
        acc[0] += cb[k] * w;
        acc[1] += cb[CATD + k] * w;
    }
    float bb = bout[col];
    out[(long)(row0 + half*2 + 0)*CS + col] = acc[0] + bb;
    out[(long)(row0 + half*2 + 1)*CS + col] = acc[1] + bb;
}

// ---------------- launcher ----------------------------------------------------
extern "C" void kernel_launch(void* const* d_in, const int* in_sizes, int n_in,
                              void* d_out, int out_size)
{
    const float* s    = (const float*)d_in[0];
    const float* R    = (const float*)d_in[1];
    const float* t    = (const float*)d_in[2];
    const float* mask = (const float*)d_in[3];
    const float* Wq   = (const float*)d_in[4];
    const float* bq   = (const float*)d_in[5];
    const float* Wkv  = (const float*)d_in[6];
    const float* bkv  = (const float*)d_in[7];
    const float* Wqp  = (const float*)d_in[8];
    const float* bqp  = (const float*)d_in[9];
    const float* Wkvp = (const float*)d_in[10];
    const float* bkvp = (const float*)d_in[11];
    const float* hwts = (const float*)d_in[12];
    const float* Wout = (const float*)d_in[13];
    const float* bout = (const float*)d_in[14];
    float* out = (float*)d_out;

    proj_kernel<<<dim3((BB*NN)/PR, 3), 256>>>(s, R, t, Wq, bq, Wkv, bkv, Wqp, bqp, Wkvp, bkvp);
    attn_kernel<<<dim3(NN/16, HH, BB), 256>>>(mask, R, t, hwts);
    out_kernel<<<(BB*NN)/4, 256>>>(Wout, bout, out);
}

// round 4
// speedup vs baseline: 1.4974x; 1.1999x over previous
#include <cuda_runtime.h>
#include <math.h>

#define BB 2
#define NN 512
#define CS 128
#define CH 16
#define HH 12
#define PQ 4
#define VV 8
#define HC (HH*CH)            /* 192 */
#define CATD (HH*(CH+VV*4))   /* 576 */

// ---------------- scratch (device globals; no allocations allowed) -----------
__device__ float q_g  [BB*HH*NN*CH];
__device__ float k_g  [BB*HH*NN*CH];
__device__ float v_g  [BB*HH*NN*CH];
__device__ float qp_g [BB*HH*NN*PQ*3];
__device__ float kp_g [BB*HH*NN*PQ*3];
__device__ float vp_g [BB*HH*NN*VV*3];
__device__ float sqq_g[BB*HH*NN];
__device__ float sqk_g[BB*HH*NN];
__device__ float cat_g[BB*NN*CATD];

// ---------------- kernel 1: projections + frame rotation --------------------
// 8 rows per block, 384 threads, 2 tasks/thread, single wave (128 blocks).
#define PR 8
__global__ __launch_bounds__(384) void proj_kernel(
    const float* __restrict__ s,  const float* __restrict__ R,
    const float* __restrict__ t,
    const float* __restrict__ Wq,  const float* __restrict__ bq,
    const float* __restrict__ Wkv, const float* __restrict__ bkv,
    const float* __restrict__ Wqp, const float* __restrict__ bqp,
    const float* __restrict__ Wkvp,const float* __restrict__ bkvp)
{
    __shared__ float s_sm[PR][CS];
    __shared__ float Rt_sm[PR][12];
    __shared__ float sqq_sm[PR][HH];
    __shared__ float sqk_sm[PR][HH];

    const int tid  = threadIdx.x;
    const int row0 = blockIdx.x * PR;

    for (int idx = tid; idx < PR*CS; idx += 384)
        s_sm[idx>>7][idx&127] = s[(long)row0*CS + idx];
    if (tid < PR*12) {
        int r = tid/12, c = tid%12;
        Rt_sm[r][c] = (c < 9) ? R[(long)(row0+r)*9 + c] : t[(long)(row0+r)*3 + (c-9)];
    }
    if (tid < PR*HH) {
        sqq_sm[tid/HH][tid%HH] = 0.f;
        sqk_sm[tid/HH][tid%HH] = 0.f;
    }
    __syncthreads();

    #pragma unroll
    for (int tt = 0; tt < 2; tt++) {
        const int task = tid + tt*384;   // 0..767
        if (task < 576) {
            const float* W; float bias; int stride; int col;
            if (task < 192) { col = task;       W = Wq  + col; stride = HC;   bias = bq[col];  }
            else            { col = task - 192; W = Wkv + col; stride = 2*HC; bias = bkv[col]; }
            float acc[PR];
            #pragma unroll
            for (int r = 0; r < PR; r++) acc[r] = bias;
            #pragma unroll 8
            for (int k = 0; k < CS; k++) {
                float w = __ldg(&W[(long)k*stride]);
                #pragma unroll
                for (int r = 0; r < PR; r++) acc[r] += w * s_sm[r][k];
            }
            if (task < 192) {
                int h = col >> 4, c = col & 15;
                #pragma unroll
                for (int r = 0; r < PR; r++) {
                    int row = row0 + r, b = row >> 9, n = row & 511;
                    q_g[((long)(b*HH+h)*NN + n)*CH + c] = acc[r];
                }
            } else {
                int h = col >> 5, cc = col & 31;
                #pragma unroll
                for (int r = 0; r < PR; r++) {
                    int row = row0 + r, b = row >> 9, n = row & 511;
                    long base = ((long)(b*HH+h)*NN + n)*CH;
                    if (cc < 16) k_g[base + cc]        = acc[r];
                    else         v_g[base + (cc-16)]   = acc[r];
                }
            }
        } else {
            int p; const float* W; int npts; const float* bvec; int is_qp;
            if (task < 624) { p = task - 576; W = Wqp;  npts = 48;  bvec = bqp;  is_qp = 1; }
            else            { p = task - 624; W = Wkvp; npts = 144; bvec = bkvp; is_qp = 0; }
            float d0[PR], d1[PR], d2[PR];
            float b0 = bvec[0*npts+p], b1 = bvec[1*npts+p], b2 = bvec[2*npts+p];
            #pragma unroll
            for (int r = 0; r < PR; r++) { d0[r] = b0; d1[r] = b1; d2[r] = b2; }
            #pragma unroll 4
            for (int k = 0; k < CS; k++) {
                float w0 = __ldg(&W[(long)k*3*npts + 0*npts + p]);
                float w1 = __ldg(&W[(long)k*3*npts + 1*npts + p]);
                float w2 = __ldg(&W[(long)k*3*npts + 2*npts + p]);
                #pragma unroll
                for (int r = 0; r < PR; r++) {
                    float sv = s_sm[r][k];
                    d0[r] += w0*sv; d1[r] += w1*sv; d2[r] += w2*sv;
                }
            }
            #pragma unroll
            for (int r = 0; r < PR; r++) {
                int row = row0 + r, b = row >> 9, n = row & 511;
                float x0 = Rt_sm[r][0]*d0[r] + Rt_sm[r][1]*d1[r] + Rt_sm[r][2]*d2[r] + Rt_sm[r][9];
                float x1 = Rt_sm[r][3]*d0[r] + Rt_sm[r][4]*d1[r] + Rt_sm[r][5]*d2[r] + Rt_sm[r][10];
                float x2 = Rt_sm[r][6]*d0[r] + Rt_sm[r][7]*d1[r] + Rt_sm[r][8]*d2[r] + Rt_sm[r][11];
                if (is_qp) {
                    int h = p / PQ, pp = p % PQ;
                    long base = ((long)(b*HH+h)*NN + n)*(PQ*3) + pp*3;
                    qp_g[base+0] = x0; qp_g[base+1] = x1; qp_g[base+2] = x2;
                    atomicAdd(&sqq_sm[r][h], x0*x0 + x1*x1 + x2*x2);
                } else {
                    int h = p / (PQ+VV), idx = p % (PQ+VV);
                    if (idx < PQ) {
                        long base = ((long)(b*HH+h)*NN + n)*(PQ*3) + idx*3;
                        kp_g[base+0] = x0; kp_g[base+1] = x1; kp_g[base+2] = x2;
                        atomicAdd(&sqk_sm[r][h], x0*x0 + x1*x1 + x2*x2);
                    } else {
                        long base = ((long)(b*HH+h)*NN + n)*(VV*3) + (idx-PQ)*3;
                        vp_g[base+0] = x0; vp_g[base+1] = x1; vp_g[base+2] = x2;
                    }
                }
            }
        }
    }
    __syncthreads();
    if (tid < PR*HH) {
        int r = tid/HH, h = tid%HH;
        int row = row0 + r, b = row >> 9, n = row & 511;
        sqq_g[(long)(b*HH+h)*NN + n] = sqq_sm[r][h];
        sqk_g[(long)(b*HH+h)*NN + n] = sqk_sm[r][h];
    }
}

// ---------------- kernel 2: attention (two-phase, channel-split phase B) -----
#define SKV 20   /* k/v tile stride in floats (float4 stride 5, odd) */
#define SKP 12   /* kp stride (float4 stride 3, odd) */
#define SVP 28   /* vp stride (float4 stride 7, odd) */

__global__ __launch_bounds__(256) void attn_kernel(
    const float* __restrict__ pair_mask,
    const float* __restrict__ R, const float* __restrict__ t,
    const float* __restrict__ head_weights)
{
    // phase A: ks[0..2559], kps[2560..4095], sqks[4096..4223], msk[4224..6271]
    // phase B1: vs[0..2559]   phase B2: vps[0..3583]
    __shared__ __align__(16) float pool[6272];
    __shared__ float red[8][2][41];
    float* const ks   = pool;
    float* const kps  = pool + 2560;
    float* const sqks = pool + 4096;
    float* const msk  = pool + 4224;
    float* const vs   = pool;
    float* const vps  = pool;

    const int tid  = threadIdx.x;
    const int lane = tid & 31;
    const int warp = tid >> 5;
    const int b = blockIdx.z, h = blockIdx.y;
    const int i0 = blockIdx.x*16 + warp*2;
    const int bh = b*HH + h;

    const float hwv = log1pf(__expf(head_weights[h])) * 0.1360827634879543f; // sqrt(1/54)
    const float c1  = -0.5f * hwv;
    const float qs  = 0.14433756729740643f;  // 1/sqrt(48)

    float la0[16], la1[16];

    // ---------------- phase A: all logits ----------------
    {
        float q0[CH], q1[CH], qp0[12], qp1[12];
        {
            const float4* qr0 = (const float4*)(q_g + ((long)bh*NN + i0)*CH);
            const float4* qr1 = (const float4*)(q_g + ((long)bh*NN + i0+1)*CH);
            #pragma unroll
            for (int c = 0; c < 4; c++) {
                float4 a = qr0[c];
                q0[4*c]=a.x*qs; q0[4*c+1]=a.y*qs; q0[4*c+2]=a.z*qs; q0[4*c+3]=a.w*qs;
                float4 d = qr1[c];
                q1[4*c]=d.x*qs; q1[4*c+1]=d.y*qs; q1[4*c+2]=d.z*qs; q1[4*c+3]=d.w*qs;
            }
            const float4* pr0 = (const float4*)(qp_g + ((long)bh*NN + i0)*12);
            const float4* pr1 = (const float4*)(qp_g + ((long)bh*NN + i0+1)*12);
            #pragma unroll
            for (int c = 0; c < 3; c++) {
                float4 a = pr0[c];
                qp0[4*c]=a.x*hwv; qp0[4*c+1]=a.y*hwv; qp0[4*c+2]=a.z*hwv; qp0[4*c+3]=a.w*hwv;
                float4 d = pr1[c];
                qp1[4*c]=d.x*hwv; qp1[4*c+1]=d.y*hwv; qp1[4*c+2]=d.z*hwv; qp1[4*c+3]=d.w*hwv;
            }
        }
        const float base0 = c1 * sqq_g[(long)bh*NN + i0];
        const float base1 = c1 * sqq_g[(long)bh*NN + i0+1];

        #pragma unroll
        for (int jt = 0; jt < 4; jt++) {
            const int j0 = jt * 128;
            __syncthreads();
            {
                const float4* kb  = (const float4*)(k_g  + ((long)bh*NN + j0)*CH);
                for (int idx = tid; idx < 512; idx += 256)
                    ((float4*)(ks + (idx>>2)*SKV))[idx&3] = kb[idx];
                const float4* kpb = (const float4*)(kp_g + ((long)bh*NN + j0)*12);
                for (int idx = tid; idx < 384; idx += 256) {
                    int j = idx/3, c = idx - j*3;
                    ((float4*)(kps + j*SKP))[c] = kpb[idx];
                }
                if (tid < 128) sqks[tid] = sqk_g[(long)bh*NN + j0 + tid];
                const long mbase = ((long)b*NN + blockIdx.x*16)*NN + j0;
                const float4* mb = (const float4*)(pair_mask + mbase);
                for (int idx = tid; idx < 512; idx += 256) {
                    int r = idx >> 5, c = idx & 31;
                    float4 mm = mb[(r*NN>>2) + c];
                    float4 o;
                    o.x = 100000.f*(mm.x-1.f); o.y = 100000.f*(mm.y-1.f);
                    o.z = 100000.f*(mm.z-1.f); o.w = 100000.f*(mm.w-1.f);
                    ((float4*)(msk + r*128))[c] = o;
                }
            }
            __syncthreads();

            #pragma unroll
            for (int u = 0; u < 4; u++) {
                const int j = u*32 + lane;
                const float4* k4  = (const float4*)(ks  + j*SKV);
                const float4* kp4 = (const float4*)(kps + j*SKP);
                float qk0 = 0.f, qk1 = 0.f;
                #pragma unroll
                for (int c = 0; c < 4; c++) {
                    float4 kk = k4[c];
                    qk0 += q0[4*c]*kk.x + q0[4*c+1]*kk.y + q0[4*c+2]*kk.z + q0[4*c+3]*kk.w;
                    qk1 += q1[4*c]*kk.x + q1[4*c+1]*kk.y + q1[4*c+2]*kk.z + q1[4*c+3]*kk.w;
                }
                #pragma unroll
                for (int c = 0; c < 3; c++) {
                    float4 kk = kp4[c];
                    qk0 += qp0[4*c]*kk.x + qp0[4*c+1]*kk.y + qp0[4*c+2]*kk.z + qp0[4*c+3]*kk.w;
                    qk1 += qp1[4*c]*kk.x + qp1[4*c+1]*kk.y + qp1[4*c+2]*kk.z + qp1[4*c+3]*kk.w;
                }
                const float skc = c1 * sqks[j];
                la0[jt*4+u] = qk0 + skc + base0 + msk[(warp*2+0)*128 + j];
                la1[jt*4+u] = qk1 + skc + base1 + msk[(warp*2+1)*128 + j];
            }
        }
    }

    // ---------------- exact softmax (max, exp, sum) ----------------
    float ls0, ls1;
    {
        float M0 = la0[0], M1 = la1[0];
        #pragma unroll
        for (int x = 1; x < 16; x++) { M0 = fmaxf(M0, la0[x]); M1 = fmaxf(M1, la1[x]); }
        #pragma unroll
        for (int o = 16; o; o >>= 1) {
            M0 = fmaxf(M0, __shfl_xor_sync(0xffffffffu, M0, o));
            M1 = fmaxf(M1, __shfl_xor_sync(0xffffffffu, M1, o));
        }
        ls0 = 0.f; ls1 = 0.f;
        #pragma unroll
        for (int x = 0; x < 16; x++) {
            la0[x] = __expf(la0[x] - M0); ls0 += la0[x];
            la1[x] = __expf(la1[x] - M1); ls1 += la1[x];
        }
    }

    // ---------------- phase B pass 1: o = A @ v (16 channels) ----------------
    {
        float av0[16], av1[16];
        #pragma unroll
        for (int x = 0; x < 16; x++) { av0[x] = 0.f; av1[x] = 0.f; }

        #pragma unroll
        for (int jt = 0; jt < 4; jt++) {
            const int j0 = jt * 128;
            __syncthreads();
            {
                const float4* vb = (const float4*)(v_g + ((long)bh*NN + j0)*CH);
                for (int idx = tid; idx < 512; idx += 256)
                    ((float4*)(vs + (idx>>2)*SKV))[idx&3] = vb[idx];
            }
            __syncthreads();

            #pragma unroll
            for (int u = 0; u < 4; u++) {
                const int j = u*32 + lane;
                const float p0 = la0[jt*4+u];
                const float p1 = la1[jt*4+u];
                const float4* v4 = (const float4*)(vs + j*SKV);
                #pragma unroll
                for (int c = 0; c < 4; c++) {
                    float4 vv = v4[c];
                    av0[4*c]   += p0*vv.x; av0[4*c+1] += p0*vv.y;
                    av0[4*c+2] += p0*vv.z; av0[4*c+3] += p0*vv.w;
                    av1[4*c]   += p1*vv.x; av1[4*c+1] += p1*vv.y;
                    av1[4*c+2] += p1*vv.z; av1[4*c+3] += p1*vv.w;
                }
            }
        }
        // reduce + stash
        float lss = ls0;
        #pragma unroll
        for (int o = 16; o; o >>= 1) lss += __shfl_xor_sync(0xffffffffu, lss, o);
        if (lane == 0) red[warp][0][40] = lss;
        lss = ls1;
        #pragma unroll
        for (int o = 16; o; o >>= 1) lss += __shfl_xor_sync(0xffffffffu, lss, o);
        if (lane == 0) red[warp][1][40] = lss;
        #pragma unroll
        for (int x = 0; x < 16; x++) {
            float v0 = av0[x], v1 = av1[x];
            #pragma unroll
            for (int o = 16; o; o >>= 1) {
                v0 += __shfl_xor_sync(0xffffffffu, v0, o);
                v1 += __shfl_xor_sync(0xffffffffu, v1, o);
            }
            if (lane == 0) { red[warp][0][x] = v0; red[warp][1][x] = v1; }
        }
    }

    // ---------------- phase B pass 2: o_pt = A @ vp (24 channels) ------------
    {
        float ap0[24], ap1[24];
        #pragma unroll
        for (int x = 0; x < 24; x++) { ap0[x] = 0.f; ap1[x] = 0.f; }

        #pragma unroll
        for (int jt = 0; jt < 4; jt++) {
            const int j0 = jt * 128;
            __syncthreads();
            {
                const float4* vpb = (const float4*)(vp_g + ((long)bh*NN + j0)*24);
                for (int idx = tid; idx < 768; idx += 256) {
                    int j = idx/6, c = idx - j*6;
                    ((float4*)(vps + j*SVP))[c] = vpb[idx];
                }
            }
            __syncthreads();

            #pragma unroll
            for (int u = 0; u < 4; u++) {
                const int j = u*32 + lane;
                const float p0 = la0[jt*4+u];
                const float p1 = la1[jt*4+u];
                const float4* vp4 = (const float4*)(vps + j*SVP);
                #pragma unroll
                for (int c = 0; c < 6; c++) {
                    float4 vv = vp4[c];
                    ap0[4*c]   += p0*vv.x; ap0[4*c+1] += p0*vv.y;
                    ap0[4*c+2] += p0*vv.z; ap0[4*c+3] += p0*vv.w;
                    ap1[4*c]   += p1*vv.x; ap1[4*c+1] += p1*vv.y;
                    ap1[4*c+2] += p1*vv.z; ap1[4*c+3] += p1*vv.w;
                }
            }
        }
        #pragma unroll
        for (int x = 0; x < 24; x++) {
            float v0 = ap0[x], v1 = ap1[x];
            #pragma unroll
            for (int o = 16; o; o >>= 1) {
                v0 += __shfl_xor_sync(0xffffffffu, v0, o);
                v1 += __shfl_xor_sync(0xffffffffu, v1, o);
            }
            if (lane == 0) { red[warp][0][16+x] = v0; red[warp][1][16+x] = v1; }
        }
    }
    __syncwarp();

    // ---------------- finalize ----------------
    #pragma unroll
    for (int ii = 0; ii < 2; ii++) {
        const int i = i0 + ii;
        const float sinv = 1.f / red[warp][ii][40];
        const long rowbase = ((long)(b*NN + i))*CATD;
        if (lane < 16) {
            cat_g[rowbase + h*CH + lane] = red[warp][ii][lane] * sinv;
        } else if (lane < 24) {
            const int vv = lane - 16;
            float gx = red[warp][ii][16 + vv*3 + 0] * sinv;
            float gy = red[warp][ii][16 + vv*3 + 1] * sinv;
            float gz = red[warp][ii][16 + vv*3 + 2] * sinv;
            const float* Rr = R + ((long)(b*NN + i))*9;
            const float* tr = t + ((long)(b*NN + i))*3;
            float lx = Rr[0]*gx + Rr[3]*gy + Rr[6]*gz - tr[0];
            float ly = Rr[1]*gx + Rr[4]*gy + Rr[7]*gz - tr[1];
            float lz = Rr[2]*gx + Rr[5]*gy + Rr[8]*gz - tr[2];
            float nrm = sqrtf(lx*lx + ly*ly + lz*lz + 1e-8f);
            cat_g[rowbase + HC +   0 + h*VV + vv] = lx;
            cat_g[rowbase + HC +  96 + h*VV + vv] = ly;
            cat_g[rowbase + HC + 192 + h*VV + vv] = lz;
            cat_g[rowbase + HC + 288 + h*VV + vv] = nrm;
        }
    }
}

// ---------------- kernel 3: output projection (8 rows/block, single wave) ----
__global__ __launch_bounds__(256) void out_kernel(
    const float* __restrict__ Wout, const float* __restrict__ bout,
    float* __restrict__ out)
{
    __shared__ float csm[8*CATD];
    const int tid  = threadIdx.x;
    const int col  = tid & 127;
    const int half = tid >> 7;        // 0 or 1: rows 0-3 vs 4-7
    const int row0 = blockIdx.x * 8;

    for (int idx = tid; idx < 8*CATD; idx += 256)
        csm[idx] = cat_g[(long)row0*CATD + idx];
    __syncthreads();

    float acc[4] = {0.f, 0.f, 0.f, 0.f};
    const float* cb = csm + half*4*CATD;
    #pragma unroll 8
    for (int k = 0; k < CATD; k++) {
        float w = __ldg(&Wout[(long)k*CS + col]);
        #pragma unroll
        for (int r = 0; r < 4; r++) acc[r] += cb[r*CATD + k] * w;
    }
    float bb = bout[col];
    #pragma unroll
    for (int r = 0; r < 4; r++)
        out[(long)(row0 + half*4 + r)*CS + col] = acc[r] + bb;
}

// ---------------- launcher ----------------------------------------------------
extern "C" void kernel_launch(void* const* d_in, const int* in_sizes, int n_in,
                              void* d_out, int out_size)
{
    const float* s    = (const float*)d_in[0];
    const float* R    = (const float*)d_in[1];
    const float* t    = (const float*)d_in[2];
    const float* mask = (const float*)d_in[3];
    const float* Wq   = (const float*)d_in[4];
    const float* bq   = (const float*)d_in[5];
    const float* Wkv  = (const float*)d_in[6];
    const float* bkv  = (const float*)d_in[7];
    const float* Wqp  = (const float*)d_in[8];
    const float* bqp  = (const float*)d_in[9];
    const float* Wkvp = (const float*)d_in[10];
    const float* bkvp = (const float*)d_in[11];
    const float* hwts = (const float*)d_in[12];
    const float* Wout = (const float*)d_in[13];
    const float* bout = (const float*)d_in[14];
    float* out = (float*)d_out;

    proj_kernel<<<(BB*NN)/PR, 384>>>(s, R, t, Wq, bq, Wkv, bkv, Wqp, bqp, Wkvp, bkvp);
    attn_kernel<<<dim3(NN/16, HH, BB), 256>>>(mask, R, t, hwts);
    out_kernel<<<(BB*NN)/8, 256>>>(Wout, bout, out);
}

// round 5
// speedup vs baseline: 1.8681x; 1.2476x over previous
#include <cuda_runtime.h>
#include <cuda_pipeline_primitives.h>
#include <math.h>

#define BB 2
#define NN 512
#define CS 128
#define CH 16
#define HH 12
#define PQ 4
#define VV 8
#define HC (HH*CH)            /* 192 */
#define CATD (HH*(CH+VV*4))   /* 576 */

// ---------------- scratch (device globals; no allocations allowed) -----------
__device__ float q_g  [BB*HH*NN*CH];
__device__ float k_g  [BB*HH*NN*CH];
__device__ float v_g  [BB*HH*NN*CH];
__device__ float qp_g [BB*HH*NN*PQ*3];
__device__ float kp_g [BB*HH*NN*PQ*3];
__device__ float vp_g [BB*HH*NN*VV*3];
__device__ float sqq_g[BB*HH*NN];
__device__ float sqk_g[BB*HH*NN];
__device__ float cat_g[BB*NN*CATD];

// ---------------- kernel 1: unified projection GEMM + rotation ---------------
// One [1024 x 128] @ [128 x 1152] GEMM; 288 threads x 4 cols, 4 rows/block.
#define PR 4
__global__ __launch_bounds__(288) void proj_kernel(
    const float* __restrict__ s,  const float* __restrict__ R,
    const float* __restrict__ t,
    const float* __restrict__ Wq,  const float* __restrict__ bq,
    const float* __restrict__ Wkv, const float* __restrict__ bkv,
    const float* __restrict__ Wqp, const float* __restrict__ bqp,
    const float* __restrict__ Wkvp,const float* __restrict__ bkvp)
{
    __shared__ float4 s4_sm[PR][32];        // s rows as float4
    __shared__ float  raw_sm[PR][576];      // raw point projections
    __shared__ float  Rt_sm[PR][12];
    __shared__ float  sqq_sm[PR][HH];
    __shared__ float  sqk_sm[PR][HH];

    const int tid  = threadIdx.x;
    const int row0 = blockIdx.x * PR;

    for (int idx = tid; idx < PR*32; idx += 288)
        s4_sm[idx>>5][idx&31] = ((const float4*)s)[(long)row0*32 + idx];
    if (tid < PR*12) {
        int r = tid/12, c = tid%12;
        Rt_sm[r][c] = (c < 9) ? R[(long)(row0+r)*9 + c] : t[(long)(row0+r)*3 + (c-9)];
    }
    if (tid < PR*HH) {
        sqq_sm[tid/HH][tid%HH] = 0.f;
        sqk_sm[tid/HH][tid%HH] = 0.f;
    }
    __syncthreads();

    // ---- GEMM: each thread owns 4 consecutive cols of the 1152-wide output --
    {
        const int col = tid * 4;           // 0..1148
        const float* Wb; const float* bb; int stride; int lcol;
        if (col < 192)      { Wb = Wq;   bb = bq;   stride = 192; lcol = col;       }
        else if (col < 576) { Wb = Wkv;  bb = bkv;  stride = 384; lcol = col - 192; }
        else if (col < 720) { Wb = Wqp;  bb = bqp;  stride = 144; lcol = col - 576; }
        else                { Wb = Wkvp; bb = bkvp; stride = 432; lcol = col - 720; }
        const int s4 = stride >> 2;
        const float4* Wp = (const float4*)Wb + (lcol >> 2);
        const float4 bias4 = __ldg((const float4*)(bb + lcol));

        float4 acc[PR];
        #pragma unroll
        for (int r = 0; r < PR; r++) acc[r] = bias4;

        #pragma unroll 4
        for (int kc = 0; kc < 32; kc++) {
            float4 sv[PR];
            #pragma unroll
            for (int r = 0; r < PR; r++) sv[r] = s4_sm[r][kc];
            #pragma unroll
            for (int qq = 0; qq < 4; qq++) {
                float4 w = __ldg(Wp + (kc*4+qq)*s4);
                #pragma unroll
                for (int r = 0; r < PR; r++) {
                    float sc = (qq==0)?sv[r].x:((qq==1)?sv[r].y:((qq==2)?sv[r].z:sv[r].w));
                    acc[r].x += w.x*sc; acc[r].y += w.y*sc;
                    acc[r].z += w.z*sc; acc[r].w += w.w*sc;
                }
            }
        }

        if (col < 192) {
            int h = col >> 4, c = col & 15;
            #pragma unroll
            for (int r = 0; r < PR; r++) {
                int row = row0 + r, b = row >> 9, n = row & 511;
                *(float4*)&q_g[((long)(b*HH+h)*NN + n)*CH + c] = acc[r];
            }
        } else if (col < 576) {
            int lc = col - 192;
            int h = lc >> 5, cc = lc & 31;
            #pragma unroll
            for (int r = 0; r < PR; r++) {
                int row = row0 + r, b = row >> 9, n = row & 511;
                long base = ((long)(b*HH+h)*NN + n)*CH;
                if (cc < 16) *(float4*)&k_g[base + cc]      = acc[r];
                else         *(float4*)&v_g[base + (cc-16)] = acc[r];
            }
        } else {
            int pc = col - 576;   // 0..575
            #pragma unroll
            for (int r = 0; r < PR; r++)
                *(float4*)&raw_sm[r][pc] = acc[r];
        }
    }
    __syncthreads();

    // ---- rotation + squared-norm pass (768 point-tasks) ----
    for (int pt = tid; pt < PR*192; pt += 288) {
        const int r = pt / 192, p = pt % 192;
        const int row = row0 + r, b = row >> 9, n = row & 511;
        float d0, d1, d2; int is_qp, h, idx;
        if (p < 48) {        // qp: layout [3][48] at raw offset 0
            d0 = raw_sm[r][p]; d1 = raw_sm[r][48+p]; d2 = raw_sm[r][96+p];
            is_qp = 1; h = p >> 2; idx = p & 3;
        } else {             // kvp: layout [3][144] at raw offset 144
            int pk = p - 48;
            d0 = raw_sm[r][144+pk]; d1 = raw_sm[r][288+pk]; d2 = raw_sm[r][432+pk];
            is_qp = 0; h = pk / 12; idx = pk % 12;
        }
        float x0 = Rt_sm[r][0]*d0 + Rt_sm[r][1]*d1 + Rt_sm[r][2]*d2 + Rt_sm[r][9];
        float x1 = Rt_sm[r][3]*d0 + Rt_sm[r][4]*d1 + Rt_sm[r][5]*d2 + Rt_sm[r][10];
        float x2 = Rt_sm[r][6]*d0 + Rt_sm[r][7]*d1 + Rt_sm[r][8]*d2 + Rt_sm[r][11];
        if (is_qp) {
            long base = ((long)(b*HH+h)*NN + n)*(PQ*3) + idx*3;
            qp_g[base+0] = x0; qp_g[base+1] = x1; qp_g[base+2] = x2;
            atomicAdd(&sqq_sm[r][h], x0*x0 + x1*x1 + x2*x2);
        } else if (idx < PQ) {
            long base = ((long)(b*HH+h)*NN + n)*(PQ*3) + idx*3;
            kp_g[base+0] = x0; kp_g[base+1] = x1; kp_g[base+2] = x2;
            atomicAdd(&sqk_sm[r][h], x0*x0 + x1*x1 + x2*x2);
        } else {
            long base = ((long)(b*HH+h)*NN + n)*(VV*3) + (idx-PQ)*3;
            vp_g[base+0] = x0; vp_g[base+1] = x1; vp_g[base+2] = x2;
        }
    }
    __syncthreads();
    if (tid < PR*HH) {
        int r = tid/HH, h = tid%HH;
        int row = row0 + r, b = row >> 9, n = row & 511;
        sqq_g[(long)(b*HH+h)*NN + n] = sqq_sm[r][h];
        sqk_g[(long)(b*HH+h)*NN + n] = sqk_sm[r][h];
    }
}

// ---------------- kernel 2: attention (two-phase, double-buffered cp.async) --
#define SKV 20   /* k/v tile stride in floats */
#define SKP 12   /* kp stride */
#define SVP 28   /* vp stride */
#define BUF 4096 /* float offset between buffers */

__global__ __launch_bounds__(256) void attn_kernel(
    const float* __restrict__ pair_mask,
    const float* __restrict__ R, const float* __restrict__ t,
    const float* __restrict__ head_weights)
{
    __shared__ __align__(16) float pool[2*BUF];   // 32 KB, double buffered
    __shared__ float red[8][2][41];

    const int tid  = threadIdx.x;
    const int lane = tid & 31;
    const int warp = tid >> 5;
    const int b = blockIdx.z, h = blockIdx.y;
    const int i0 = blockIdx.x*16 + warp*2;
    const int bh = b*HH + h;

    const float hwv = log1pf(__expf(head_weights[h])) * 0.1360827634879543f; // sqrt(1/54)
    const float c1  = -0.5f * hwv;
    const float qs  = 0.14433756729740643f;  // 1/sqrt(48)

    const float* kbase  = k_g  + (long)bh*NN*CH;
    const float* vbase  = v_g  + (long)bh*NN*CH;
    const float* kpbase = kp_g + (long)bh*NN*12;
    const float* vpbase = vp_g + (long)bh*NN*24;
    const float* sqkrow = sqk_g + (long)bh*NN;
    const float* mrow0  = pair_mask + ((long)b*NN + i0)*NN;
    const float* mrow1  = mrow0 + NN;

    float la0[16], la1[16];

    // ================= phase A: all logits =================
    {
        float q0[CH], q1[CH], qp0[12], qp1[12];
        {
            const float4* qr0 = (const float4*)(q_g + ((long)bh*NN + i0)*CH);
            const float4* qr1 = (const float4*)(q_g + ((long)bh*NN + i0+1)*CH);
            #pragma unroll
            for (int c = 0; c < 4; c++) {
                float4 a = qr0[c];
                q0[4*c]=a.x*qs; q0[4*c+1]=a.y*qs; q0[4*c+2]=a.z*qs; q0[4*c+3]=a.w*qs;
                float4 d = qr1[c];
                q1[4*c]=d.x*qs; q1[4*c+1]=d.y*qs; q1[4*c+2]=d.z*qs; q1[4*c+3]=d.w*qs;
            }
            const float4* pr0 = (const float4*)(qp_g + ((long)bh*NN + i0)*12);
            const float4* pr1 = (const float4*)(qp_g + ((long)bh*NN + i0+1)*12);
            #pragma unroll
            for (int c = 0; c < 3; c++) {
                float4 a = pr0[c];
                qp0[4*c]=a.x*hwv; qp0[4*c+1]=a.y*hwv; qp0[4*c+2]=a.z*hwv; qp0[4*c+3]=a.w*hwv;
                float4 d = pr1[c];
                qp1[4*c]=d.x*hwv; qp1[4*c+1]=d.y*hwv; qp1[4*c+2]=d.z*hwv; qp1[4*c+3]=d.w*hwv;
            }
        }
        // fold -100000 into per-query base constant
        const float base0 = c1 * __ldg(&sqq_g[(long)bh*NN + i0])   - 100000.f;
        const float base1 = c1 * __ldg(&sqq_g[(long)bh*NN + i0+1]) - 100000.f;

        // prologue fill jt=0 -> buf 0
        {
            const float4* k4  = (const float4*)kbase;
            for (int idx = tid; idx < 512; idx += 256)
                __pipeline_memcpy_async(&pool[(idx>>2)*SKV + ((idx&3)<<2)], &k4[idx], 16);
            const float4* kp4 = (const float4*)kpbase;
            for (int idx = tid; idx < 384; idx += 256) {
                int j = idx/3, c = idx - j*3;
                __pipeline_memcpy_async(&pool[2560 + j*SKP + (c<<2)], &kp4[idx], 16);
            }
        }
        __pipeline_commit();

        #pragma unroll
        for (int jt = 0; jt < 4; jt++) {
            if (jt < 3) {
                float* dst = pool + ((jt+1)&1)*BUF;
                const float4* k4  = (const float4*)(kbase + (jt+1)*128*CH);
                for (int idx = tid; idx < 512; idx += 256)
                    __pipeline_memcpy_async(&dst[(idx>>2)*SKV + ((idx&3)<<2)], &k4[idx], 16);
                const float4* kp4 = (const float4*)(kpbase + (jt+1)*128*12);
                for (int idx = tid; idx < 384; idx += 256) {
                    int j = idx/3, c = idx - j*3;
                    __pipeline_memcpy_async(&dst[2560 + j*SKP + (c<<2)], &kp4[idx], 16);
                }
                __pipeline_commit();
                __pipeline_wait_prior(1);
            } else {
                __pipeline_wait_prior(0);
            }
            __syncthreads();

            const float* ks  = pool + (jt&1)*BUF;
            const float* kps = ks + 2560;
            const int j0 = jt*128;
            #pragma unroll
            for (int u = 0; u < 4; u++) {
                const int j = u*32 + lane;
                const float4* k4  = (const float4*)(ks  + j*SKV);
                const float4* kp4 = (const float4*)(kps + j*SKP);
                float qk0 = 0.f, qk1 = 0.f;
                #pragma unroll
                for (int c = 0; c < 4; c++) {
                    float4 kk = k4[c];
                    qk0 += q0[4*c]*kk.x + q0[4*c+1]*kk.y + q0[4*c+2]*kk.z + q0[4*c+3]*kk.w;
                    qk1 += q1[4*c]*kk.x + q1[4*c+1]*kk.y + q1[4*c+2]*kk.z + q1[4*c+3]*kk.w;
                }
                #pragma unroll
                for (int c = 0; c < 3; c++) {
                    float4 kk = kp4[c];
                    qk0 += qp0[4*c]*kk.x + qp0[4*c+1]*kk.y + qp0[4*c+2]*kk.z + qp0[4*c+3]*kk.w;
                    qk1 += qp1[4*c]*kk.x + qp1[4*c+1]*kk.y + qp1[4*c+2]*kk.z + qp1[4*c+3]*kk.w;
                }
                const float skc = c1 * __ldg(&sqkrow[j0 + j]);
                la0[jt*4+u] = qk0 + skc + base0 + 100000.f*__ldg(&mrow0[j0 + j]);
                la1[jt*4+u] = qk1 + skc + base1 + 100000.f*__ldg(&mrow1[j0 + j]);
            }
            __syncthreads();
        }
    }

    // ================= exact softmax =================
    float ls0, ls1;
    {
        float M0 = la0[0], M1 = la1[0];
        #pragma unroll
        for (int x = 1; x < 16; x++) { M0 = fmaxf(M0, la0[x]); M1 = fmaxf(M1, la1[x]); }
        #pragma unroll
        for (int o = 16; o; o >>= 1) {
            M0 = fmaxf(M0, __shfl_xor_sync(0xffffffffu, M0, o));
            M1 = fmaxf(M1, __shfl_xor_sync(0xffffffffu, M1, o));
        }
        ls0 = 0.f; ls1 = 0.f;
        #pragma unroll
        for (int x = 0; x < 16; x++) {
            la0[x] = __expf(la0[x] - M0); ls0 += la0[x];
            la1[x] = __expf(la1[x] - M1); ls1 += la1[x];
        }
    }
    __syncthreads();   // phase A tiles dead before B refills pool

    // ================= phase B pass 1: o = A @ v =================
    {
        float av0[16], av1[16];
        #pragma unroll
        for (int x = 0; x < 16; x++) { av0[x] = 0.f; av1[x] = 0.f; }

        {
            const float4* v4 = (const float4*)vbase;
            for (int idx = tid; idx < 512; idx += 256)
                __pipeline_memcpy_async(&pool[(idx>>2)*SKV + ((idx&3)<<2)], &v4[idx], 16);
        }
        __pipeline_commit();

        #pragma unroll
        for (int jt = 0; jt < 4; jt++) {
            if (jt < 3) {
                float* dst = pool + ((jt+1)&1)*BUF;
                const float4* v4 = (const float4*)(vbase + (jt+1)*128*CH);
                for (int idx = tid; idx < 512; idx += 256)
                    __pipeline_memcpy_async(&dst[(idx>>2)*SKV + ((idx&3)<<2)], &v4[idx], 16);
                __pipeline_commit();
                __pipeline_wait_prior(1);
            } else {
                __pipeline_wait_prior(0);
            }
            __syncthreads();

            const float* vs = pool + (jt&1)*BUF;
            #pragma unroll
            for (int u = 0; u < 4; u++) {
                const int j = u*32 + lane;
                const float p0 = la0[jt*4+u];
                const float p1 = la1[jt*4+u];
                const float4* v4 = (const float4*)(vs + j*SKV);
                #pragma unroll
                for (int c = 0; c < 4; c++) {
                    float4 vv = v4[c];
                    av0[4*c]   += p0*vv.x; av0[4*c+1] += p0*vv.y;
                    av0[4*c+2] += p0*vv.z; av0[4*c+3] += p0*vv.w;
                    av1[4*c]   += p1*vv.x; av1[4*c+1] += p1*vv.y;
                    av1[4*c+2] += p1*vv.z; av1[4*c+3] += p1*vv.w;
                }
            }
            __syncthreads();
        }
        float lss = ls0;
        #pragma unroll
        for (int o = 16; o; o >>= 1) lss += __shfl_xor_sync(0xffffffffu, lss, o);
        if (lane == 0) red[warp][0][40] = lss;
        lss = ls1;
        #pragma unroll
        for (int o = 16; o; o >>= 1) lss += __shfl_xor_sync(0xffffffffu, lss, o);
        if (lane == 0) red[warp][1][40] = lss;
        #pragma unroll
        for (int x = 0; x < 16; x++) {
            float v0 = av0[x], v1 = av1[x];
            #pragma unroll
            for (int o = 16; o; o >>= 1) {
                v0 += __shfl_xor_sync(0xffffffffu, v0, o);
                v1 += __shfl_xor_sync(0xffffffffu, v1, o);
            }
            if (lane == 0) { red[warp][0][x] = v0; red[warp][1][x] = v1; }
        }
    }

    // ================= phase B pass 2: o_pt = A @ vp =================
    {
        float ap0[24], ap1[24];
        #pragma unroll
        for (int x = 0; x < 24; x++) { ap0[x] = 0.f; ap1[x] = 0.f; }

        {
            const float4* vp4 = (const float4*)vpbase;
            for (int idx = tid; idx < 768; idx += 256) {
                int j = idx/6, c = idx - j*6;
                __pipeline_memcpy_async(&pool[j*SVP + (c<<2)], &vp4[idx], 16);
            }
        }
        __pipeline_commit();

        #pragma unroll
        for (int jt = 0; jt < 4; jt++) {
            if (jt < 3) {
                float* dst = pool + ((jt+1)&1)*BUF;
                const float4* vp4 = (const float4*)(vpbase + (jt+1)*128*24);
                for (int idx = tid; idx < 768; idx += 256) {
                    int j = idx/6, c = idx - j*6;
                    __pipeline_memcpy_async(&dst[j*SVP + (c<<2)], &vp4[idx], 16);
                }
                __pipeline_commit();
                __pipeline_wait_prior(1);
            } else {
                __pipeline_wait_prior(0);
            }
            __syncthreads();

            const float* vps = pool + (jt&1)*BUF;
            #pragma unroll
            for (int u = 0; u < 4; u++) {
                const int j = u*32 + lane;
                const float p0 = la0[jt*4+u];
                const float p1 = la1[jt*4+u];
                const float4* vp4 = (const float4*)(vps + j*SVP);
                #pragma unroll
                for (int c = 0; c < 6; c++) {
                    float4 vv = vp4[c];
                    ap0[4*c]   += p0*vv.x; ap0[4*c+1] += p0*vv.y;
                    ap0[4*c+2] += p0*vv.z; ap0[4*c+3] += p0*vv.w;
                    ap1[4*c]   += p1*vv.x; ap1[4*c+1] += p1*vv.y;
                    ap1[4*c+2] += p1*vv.z; ap1[4*c+3] += p1*vv.w;
                }
            }
            __syncthreads();
        }
        #pragma unroll
        for (int x = 0; x < 24; x++) {
            float v0 = ap0[x], v1 = ap1[x];
            #pragma unroll
            for (int o = 16; o; o >>= 1) {
                v0 += __shfl_xor_sync(0xffffffffu, v0, o);
                v1 += __shfl_xor_sync(0xffffffffu, v1, o);
            }
            if (lane == 0) { red[warp][0][16+x] = v0; red[warp][1][16+x] = v1; }
        }
    }
    __syncwarp();

    // ================= finalize =================
    #pragma unroll
    for (int ii = 0; ii < 2; ii++) {
        const int i = i0 + ii;
        const float sinv = 1.f / red[warp][ii][40];
        const long rowbase = ((long)(b*NN + i))*CATD;
        if (lane < 16) {
            cat_g[rowbase + h*CH + lane] = red[warp][ii][lane] * sinv;
        } else if (lane < 24) {
            const int vv = lane - 16;
            float gx = red[warp][ii][16 + vv*3 + 0] * sinv;
            float gy = red[warp][ii][16 + vv*3 + 1] * sinv;
            float gz = red[warp][ii][16 + vv*3 + 2] * sinv;
            const float* Rr = R + ((long)(b*NN + i))*9;
            const float* tr = t + ((long)(b*NN + i))*3;
            float lx = Rr[0]*gx + Rr[3]*gy + Rr[6]*gz - tr[0];
            float ly = Rr[1]*gx + Rr[4]*gy + Rr[7]*gz - tr[1];
            float lz = Rr[2]*gx + Rr[5]*gy + Rr[8]*gz - tr[2];
            float nrm = sqrtf(lx*lx + ly*ly + lz*lz + 1e-8f);
            cat_g[rowbase + HC +   0 + h*VV + vv] = lx;
            cat_g[rowbase + HC +  96 + h*VV + vv] = ly;
            cat_g[rowbase + HC + 192 + h*VV + vv] = lz;
            cat_g[rowbase + HC + 288 + h*VV + vv] = nrm;
        }
    }
}

// ---------------- kernel 3: output projection (8 rows/block, single wave) ----
__global__ __launch_bounds__(256) void out_kernel(
    const float* __restrict__ Wout, const float* __restrict__ bout,
    float* __restrict__ out)
{
    __shared__ float csm[8*CATD];
    const int tid  = threadIdx.x;
    const int col  = tid & 127;
    const int half = tid >> 7;
    const int row0 = blockIdx.x * 8;

    for (int idx = tid; idx < 8*CATD; idx += 256)
        csm[idx] = cat_g[(long)row0*CATD + idx];
    __syncthreads();

    float acc[4] = {0.f, 0.f, 0.f, 0.f};
    const float* cb = csm + half*4*CATD;
    #pragma unroll 8
    for (int k = 0; k < CATD; k++) {
        float w = __ldg(&Wout[(long)k*CS + col]);
        #pragma unroll
        for (int r = 0; r < 4; r++) acc[r] += cb[r*CATD + k] * w;
    }
    float bb = bout[col];
    #pragma unroll
    for (int r = 0; r < 4; r++)
        out[(long)(row0 + half*4 + r)*CS + col] = acc[r] + bb;
}

// ---------------- launcher ----------------------------------------------------
extern "C" void kernel_launch(void* const* d_in, const int* in_sizes, int n_in,
                              void* d_out, int out_size)
{
    const float* s    = (const float*)d_in[0];
    const float* R    = (const float*)d_in[1];
    const float* t    = (const float*)d_in[2];
    const float* mask = (const float*)d_in[3];
    const float* Wq   = (const float*)d_in[4];
    const float* bq   = (const float*)d_in[5];
    const float* Wkv  = (const float*)d_in[6];
    const float* bkv  = (const float*)d_in[7];
    const float* Wqp  = (const float*)d_in[8];
    const float* bqp  = (const float*)d_in[9];
    const float* Wkvp = (const float*)d_in[10];
    const float* bkvp = (const float*)d_in[11];
    const float* hwts = (const float*)d_in[12];
    const float* Wout = (const float*)d_in[13];
    const float* bout = (const float*)d_in[14];
    float* out = (float*)d_out;

    proj_kernel<<<(BB*NN)/PR, 288>>>(s, R, t, Wq, bq, Wkv, bkv, Wqp, bqp, Wkvp, bkvp);
    attn_kernel<<<dim3(NN/16, HH, BB), 256>>>(mask, R, t, hwts);
    out_kernel<<<(BB*NN)/8, 256>>>(Wout, bout, out);
}